// round 1
// baseline (speedup 1.0000x reference)
#include <cuda_runtime.h>
#include <math_constants.h>

#define BATCH 2
#define SLEN  2048
#define HID   2048
#define NH    16
#define NKV   4
#define HD    128
#define LAT   256
#define ROWS  (BATCH * SLEN)          // 4096
#define QKVLN (HID + 512 + 512 + LAT) // 3328
#define ACTN  (HID + LAT)             // 2304

// Scratch (static device globals: allocation-free per harness rules)
__device__ float g_qkvl[(size_t)ROWS * QKVLN];              // 54.5 MB
__device__ float g_Q[(size_t)BATCH * NH * SLEN * HD];       // 33.5 MB
__device__ float g_K[(size_t)BATCH * NKV * SLEN * HD];      //  8.4 MB
__device__ float g_V[(size_t)BATCH * NKV * SLEN * HD];      //  8.4 MB
__device__ float g_Act[(size_t)ROWS * ACTN];                // 37.7 MB (ctx | gate*mid)

// ---------------------------------------------------------------------------
// Generic NT SGEMM: C[M,N] = A[M,K] * B[N,K]^T
// MODE 0: A=hs (lda 2048), B = [Wq|Wk|Wv|Wl_in] selected by n-block, C=g_qkvl
// MODE 1: A=g_Act (lda 2304), B = Wo (k<2048) / Wl_out (k>=2048), C=out
// 128x128 block tile, BK=16, 256 threads, 8x8 per-thread microtile.
// ---------------------------------------------------------------------------
template <int MODE>
__global__ __launch_bounds__(256, 2)
void sgemm_nt(const float* __restrict__ A,
              const float* __restrict__ W0, const float* __restrict__ W1,
              const float* __restrict__ W2, const float* __restrict__ W3,
              float* __restrict__ C)
{
    constexpr int LDA = (MODE == 0) ? HID : ACTN;
    constexpr int LDC = (MODE == 0) ? QKVLN : HID;
    constexpr int KT  = (MODE == 0) ? HID : ACTN;

    __shared__ float As[16][132];
    __shared__ float Bs[16][132];

    const int n0  = blockIdx.x * 128;
    const int m0  = blockIdx.y * 128;
    const int tid = threadIdx.x;
    const int tx  = tid & 15;
    const int ty  = tid >> 4;
    const int lrow = tid >> 2;
    const int lc4  = (tid & 3) << 2;

    const float* Aeff = (MODE == 0) ? A : g_Act;
    float*       Ceff = (MODE == 0) ? g_qkvl : C;

    const float* Apt = Aeff + (size_t)(m0 + lrow) * LDA + lc4;

    const float* Bseg = nullptr;
    if (MODE == 0) {
        if (n0 < HID)             Bseg = W0 + (size_t)n0 * HID;
        else if (n0 < HID + 512)  Bseg = W1 + (size_t)(n0 - HID) * HID;
        else if (n0 < HID + 1024) Bseg = W2 + (size_t)(n0 - HID - 512) * HID;
        else                      Bseg = W3 + (size_t)(n0 - HID - 1024) * HID;
    }

    float acc[8][8];
#pragma unroll
    for (int i = 0; i < 8; i++)
#pragma unroll
        for (int j = 0; j < 8; j++) acc[i][j] = 0.f;

    float4 a0, a1, b0, b1;

#define LOAD_TILE(K0)                                                          \
    do {                                                                       \
        a0 = *(const float4*)(Apt + (K0));                                     \
        a1 = *(const float4*)(Apt + (size_t)64 * LDA + (K0));                  \
        const float* bp; int ldb;                                              \
        if (MODE == 0) { bp = Bseg + (K0); ldb = HID; }                        \
        else if ((K0) < HID) { bp = W0 + (size_t)n0 * HID + (K0); ldb = HID; } \
        else { bp = W1 + (size_t)n0 * LAT + ((K0) - HID); ldb = LAT; }         \
        b0 = *(const float4*)(bp + (size_t)lrow * ldb + lc4);                  \
        b1 = *(const float4*)(bp + (size_t)(lrow + 64) * ldb + lc4);           \
    } while (0)

    LOAD_TILE(0);

    for (int k0 = 0; k0 < KT; k0 += 16) {
        __syncthreads();
        As[lc4 + 0][lrow] = a0.x; As[lc4 + 1][lrow] = a0.y;
        As[lc4 + 2][lrow] = a0.z; As[lc4 + 3][lrow] = a0.w;
        As[lc4 + 0][lrow + 64] = a1.x; As[lc4 + 1][lrow + 64] = a1.y;
        As[lc4 + 2][lrow + 64] = a1.z; As[lc4 + 3][lrow + 64] = a1.w;
        Bs[lc4 + 0][lrow] = b0.x; Bs[lc4 + 1][lrow] = b0.y;
        Bs[lc4 + 2][lrow] = b0.z; Bs[lc4 + 3][lrow] = b0.w;
        Bs[lc4 + 0][lrow + 64] = b1.x; Bs[lc4 + 1][lrow + 64] = b1.y;
        Bs[lc4 + 2][lrow + 64] = b1.z; Bs[lc4 + 3][lrow + 64] = b1.w;
        __syncthreads();

        if (k0 + 16 < KT) LOAD_TILE(k0 + 16);  // prefetch next (overlaps compute)

#pragma unroll
        for (int k = 0; k < 16; k++) {
            float ar[8], br[8];
            *(float4*)&ar[0] = *(const float4*)&As[k][ty * 8];
            *(float4*)&ar[4] = *(const float4*)&As[k][ty * 8 + 4];
            *(float4*)&br[0] = *(const float4*)&Bs[k][tx * 8];
            *(float4*)&br[4] = *(const float4*)&Bs[k][tx * 8 + 4];
#pragma unroll
            for (int i = 0; i < 8; i++)
#pragma unroll
                for (int j = 0; j < 8; j++)
                    acc[i][j] = fmaf(ar[i], br[j], acc[i][j]);
        }
    }
#undef LOAD_TILE

#pragma unroll
    for (int i = 0; i < 8; i++) {
        const int m = m0 + ty * 8 + i;
        float* cp = Ceff + (size_t)m * LDC + n0 + tx * 8;
        *(float4*)cp       = make_float4(acc[i][0], acc[i][1], acc[i][2], acc[i][3]);
        *(float4*)(cp + 4) = make_float4(acc[i][4], acc[i][5], acc[i][6], acc[i][7]);
    }
}

// ---------------------------------------------------------------------------
// RoPE + repack: g_qkvl -> g_Q (b,h,s,d), g_K/g_V (b,kvh,s,d), gate*mid -> Act
// ---------------------------------------------------------------------------
__global__ __launch_bounds__(256)
void repack_rope(const float* __restrict__ cosb, const float* __restrict__ sinb,
                 const float* __restrict__ gate)
{
    const int idx = blockIdx.x * 256 + threadIdx.x;  // exact grid, no bounds check
    const int row = idx / QKVLN;
    const int n   = idx - row * QKVLN;
    const int b   = row >> 11;
    const int s   = row & 2047;
    const float v = g_qkvl[idx];

    if (n < HID) {                       // Q + RoPE
        const int head = n >> 7, d = n & 127;
        const float c = cosb[s * HD + d], sn = sinb[s * HD + d];
        const float other = (d < 64) ? -g_qkvl[idx + 64] : g_qkvl[idx - 64];
        g_Q[(((size_t)b * NH + head) * SLEN + s) * HD + d] = v * c + other * sn;
    } else if (n < HID + 512) {          // K + RoPE
        const int nn = n - HID, head = nn >> 7, d = nn & 127;
        const float c = cosb[s * HD + d], sn = sinb[s * HD + d];
        const float other = (d < 64) ? -g_qkvl[idx + 64] : g_qkvl[idx - 64];
        g_K[(((size_t)b * NKV + head) * SLEN + s) * HD + d] = v * c + other * sn;
    } else if (n < HID + 1024) {         // V copy
        const int nn = n - HID - 512, head = nn >> 7, d = nn & 127;
        g_V[(((size_t)b * NKV + head) * SLEN + s) * HD + d] = v;
    } else {                             // latent mid * gate -> Act tail
        g_Act[(size_t)row * ACTN + HID + (n - HID - 1024)] = gate[0] * v;
    }
}

// ---------------------------------------------------------------------------
// Flash attention (fp32): 64 q-rows x 64 k-cols x d=128 tiles, causal skip.
// Thread (ty 0..15, tx 0..15): scores 4x4 (m=ty*4+i, n=tx*4+j),
// ctx 4x8 (d = tx*4+j and 64+tx*4+j). Row reductions via 16-lane shuffles.
// ---------------------------------------------------------------------------
#define ATTN_SMEM ((2 * 128 * 68 + 64 * 132 + 64 * 68) * 4)  // 120832 B

__global__ __launch_bounds__(256)
void attn_kernel()
{
    extern __shared__ float sm[];
    float* Qs = sm;                   // [128 d][68] (transposed, scaled)
    float* Ks = sm + 128 * 68;        // [128 d][68]
    float* Vs = sm + 2 * 128 * 68;    // [64 n][132]
    float* Ps = Vs + 64 * 132;        // [64 m][68]

    const int qt  = (int)gridDim.x - 1 - (int)blockIdx.x;  // long blocks first
    const int bh  = blockIdx.y;
    const int b   = bh >> 4;
    const int h   = bh & 15;
    const int kvh = h >> 2;
    const int tid = threadIdx.x;
    const int tx  = tid & 15;
    const int ty  = tid >> 4;

    const float scale = 0.088388347648318447f;  // 1/sqrt(128)

    const float* Qg = g_Q + ((size_t)(b * NH + h) * SLEN + qt * 64) * HD;
    const float* Kg = g_K + (size_t)(b * NKV + kvh) * SLEN * HD;
    const float* Vg = g_V + (size_t)(b * NKV + kvh) * SLEN * HD;

#pragma unroll
    for (int i = tid; i < 64 * 32; i += 256) {
        const int r = i >> 5, c4 = (i & 31) << 2;
        float4 qv = *(const float4*)(Qg + r * HD + c4);
        Qs[(c4 + 0) * 68 + r] = qv.x * scale;
        Qs[(c4 + 1) * 68 + r] = qv.y * scale;
        Qs[(c4 + 2) * 68 + r] = qv.z * scale;
        Qs[(c4 + 3) * 68 + r] = qv.w * scale;
    }

    float acc[4][8];
    float rmax[4], rsum[4];
#pragma unroll
    for (int i = 0; i < 4; i++) {
        rmax[i] = -CUDART_INF_F; rsum[i] = 0.f;
#pragma unroll
        for (int j = 0; j < 8; j++) acc[i][j] = 0.f;
    }

    const int ntiles = qt + 1;  // causal: skip fully-masked tiles
    for (int kt = 0; kt < ntiles; kt++) {
        const float* Kt = Kg + (size_t)kt * 64 * HD;
        const float* Vt = Vg + (size_t)kt * 64 * HD;

        __syncthreads();  // prev PV done (and Q load on first iter)
#pragma unroll
        for (int i = tid; i < 64 * 32; i += 256) {
            const int r = i >> 5, c4 = (i & 31) << 2;
            float4 kv = *(const float4*)(Kt + r * HD + c4);
            Ks[(c4 + 0) * 68 + r] = kv.x;
            Ks[(c4 + 1) * 68 + r] = kv.y;
            Ks[(c4 + 2) * 68 + r] = kv.z;
            Ks[(c4 + 3) * 68 + r] = kv.w;
            *(float4*)(Vs + r * 132 + c4) = *(const float4*)(Vt + r * HD + c4);
        }
        __syncthreads();

        float s[4][4];
#pragma unroll
        for (int i = 0; i < 4; i++)
#pragma unroll
            for (int j = 0; j < 4; j++) s[i][j] = 0.f;

#pragma unroll 8
        for (int d = 0; d < 128; d++) {
            float4 qa = *(const float4*)(Qs + d * 68 + ty * 4);
            float4 kb = *(const float4*)(Ks + d * 68 + tx * 4);
            const float qr[4] = {qa.x, qa.y, qa.z, qa.w};
            const float kr[4] = {kb.x, kb.y, kb.z, kb.w};
#pragma unroll
            for (int i = 0; i < 4; i++)
#pragma unroll
                for (int j = 0; j < 4; j++)
                    s[i][j] = fmaf(qr[i], kr[j], s[i][j]);
        }

        if (kt == qt) {  // diagonal tile: causal mask
#pragma unroll
            for (int i = 0; i < 4; i++)
#pragma unroll
                for (int j = 0; j < 4; j++)
                    if (tx * 4 + j > ty * 4 + i) s[i][j] = -CUDART_INF_F;
        }

#pragma unroll
        for (int i = 0; i < 4; i++) {
            float mx = fmaxf(fmaxf(s[i][0], s[i][1]), fmaxf(s[i][2], s[i][3]));
#pragma unroll
            for (int o = 8; o > 0; o >>= 1)
                mx = fmaxf(mx, __shfl_xor_sync(0xffffffffu, mx, o));
            const float mnew = fmaxf(rmax[i], mx);
            const float corr = __expf(rmax[i] - mnew);
            rmax[i] = mnew;
            float ps = 0.f;
#pragma unroll
            for (int j = 0; j < 4; j++) {
                const float p = __expf(s[i][j] - mnew);
                s[i][j] = p; ps += p;
            }
            rsum[i] = rsum[i] * corr + ps;
#pragma unroll
            for (int j = 0; j < 8; j++) acc[i][j] *= corr;
            *(float4*)(Ps + (ty * 4 + i) * 68 + tx * 4) =
                make_float4(s[i][0], s[i][1], s[i][2], s[i][3]);
        }
        __syncthreads();

#pragma unroll 8
        for (int n = 0; n < 64; n++) {
            const float pp[4] = {Ps[(ty * 4 + 0) * 68 + n], Ps[(ty * 4 + 1) * 68 + n],
                                 Ps[(ty * 4 + 2) * 68 + n], Ps[(ty * 4 + 3) * 68 + n]};
            float4 va = *(const float4*)(Vs + n * 132 + tx * 4);
            float4 vb = *(const float4*)(Vs + n * 132 + 64 + tx * 4);
            const float vv[8] = {va.x, va.y, va.z, va.w, vb.x, vb.y, vb.z, vb.w};
#pragma unroll
            for (int i = 0; i < 4; i++)
#pragma unroll
                for (int j = 0; j < 8; j++)
                    acc[i][j] = fmaf(pp[i], vv[j], acc[i][j]);
        }
    }

#pragma unroll
    for (int i = 0; i < 4; i++) {
        float sum = rsum[i];
#pragma unroll
        for (int o = 8; o > 0; o >>= 1)
            sum += __shfl_xor_sync(0xffffffffu, sum, o);
        const float inv = 1.f / sum;
        const int m = qt * 64 + ty * 4 + i;
        float* op = g_Act + ((size_t)b * SLEN + m) * ACTN + h * HD;
        *(float4*)(op + tx * 4)      = make_float4(acc[i][0] * inv, acc[i][1] * inv,
                                                   acc[i][2] * inv, acc[i][3] * inv);
        *(float4*)(op + 64 + tx * 4) = make_float4(acc[i][4] * inv, acc[i][5] * inv,
                                                   acc[i][6] * inv, acc[i][7] * inv);
    }
}

// ---------------------------------------------------------------------------
extern "C" void kernel_launch(void* const* d_in, const int* in_sizes, int n_in,
                              void* d_out, int out_size)
{
    const float* hs     = (const float*)d_in[0];
    const float* cosb   = (const float*)d_in[1];
    const float* sinb   = (const float*)d_in[2];
    // d_in[3] = attention_mask (pure causal; implemented directly)
    const float* Wq     = (const float*)d_in[4];
    const float* Wk     = (const float*)d_in[5];
    const float* Wv     = (const float*)d_in[6];
    const float* Wo     = (const float*)d_in[7];
    const float* Wl_in  = (const float*)d_in[8];
    const float* Wl_out = (const float*)d_in[9];
    const float* gate   = (const float*)d_in[10];
    float* out = (float*)d_out;

    cudaFuncSetAttribute(attn_kernel,
                         cudaFuncAttributeMaxDynamicSharedMemorySize, ATTN_SMEM);

    // 1) fused [Q|K|V|latent_mid] projection
    sgemm_nt<0><<<dim3(QKVLN / 128, ROWS / 128), 256>>>(hs, Wq, Wk, Wv, Wl_in, nullptr);
    // 2) RoPE + repack (+ gate*mid into Act tail)
    repack_rope<<<(ROWS * QKVLN) / 256, 256>>>(cosb, sinb, gate);
    // 3) flash attention -> Act[:, 0:2048]
    attn_kernel<<<dim3(SLEN / 64, BATCH * NH), 256, ATTN_SMEM>>>();
    // 4) out = Act @ [Wo | Wl_out]^T
    sgemm_nt<1><<<dim3(HID / 128, ROWS / 128), 256>>>(nullptr, Wo, Wl_out,
                                                      nullptr, nullptr, out);
}

// round 3
// speedup vs baseline: 1.5246x; 1.5246x over previous
#include <cuda_runtime.h>
#include <cuda_bf16.h>
#include <math_constants.h>
#include <cstdint>

#define BATCH 2
#define SLEN  2048
#define HID   2048
#define NH    16
#define NKV   4
#define HD    128
#define LAT   256
#define ROWS  (BATCH * SLEN)          // 4096
#define QKVLN (HID + 512 + 512 + LAT) // 3328
#define ACTN  (HID + LAT)             // 2304

// Scratch (static device globals: allocation-free per harness rules)
__device__ float g_qkvl[(size_t)ROWS * QKVLN];
__device__ float g_Q[(size_t)BATCH * NH * SLEN * HD];
__device__ float g_K[(size_t)BATCH * NKV * SLEN * HD];
__device__ float g_V[(size_t)BATCH * NKV * SLEN * HD];
__device__ float g_Act[(size_t)ROWS * ACTN];

// ---------------------------------------------------------------------------
// mma.sync helpers (base sm_103-legal: no tcgen05/TMEM — harness PTX targets
// sm_103 without the 'a' feature set)
// ---------------------------------------------------------------------------
__device__ __forceinline__ uint32_t smem_u32(const void* p) {
    uint32_t a;
    asm("{ .reg .u64 t; cvta.to.shared.u64 t, %1; cvt.u32.u64 %0, t; }"
        : "=r"(a) : "l"(p));
    return a;
}
__device__ __forceinline__ void ldm_x4(uint32_t& r0, uint32_t& r1,
                                       uint32_t& r2, uint32_t& r3, uint32_t addr) {
    asm volatile("ldmatrix.sync.aligned.m8n8.x4.shared.b16 {%0,%1,%2,%3}, [%4];"
                 : "=r"(r0), "=r"(r1), "=r"(r2), "=r"(r3) : "r"(addr));
}
__device__ __forceinline__ void mma16816(float* c, const uint32_t* a, const uint32_t* b) {
    asm volatile(
        "mma.sync.aligned.m16n8k16.row.col.f32.bf16.bf16.f32 "
        "{%0,%1,%2,%3}, {%4,%5,%6,%7}, {%8,%9}, {%0,%1,%2,%3};"
        : "+f"(c[0]), "+f"(c[1]), "+f"(c[2]), "+f"(c[3])
        : "r"(a[0]), "r"(a[1]), "r"(a[2]), "r"(a[3]), "r"(b[0]), "r"(b[1]));
}
__device__ __forceinline__ uint32_t pack_bf16(float lo, float hi) {
    uint32_t r;
    asm("cvt.rn.bf16x2.f32 %0, %1, %2;" : "=r"(r) : "f"(hi), "f"(lo));
    return r;
}

// ---------------------------------------------------------------------------
// bf16 split-precision NT GEMM on mma.sync: C[M,N] = A[M,K] * B[N,K]^T
// 128x128 CTA tile, BK=32, 8 warps (2x4), warp tile 64x32 (4x4 m16n8k16).
// A = Ahi + Alo, B = Bhi + Blo; D += AhiBhi + AhiBlo + AloBhi (err ~4e-6).
// SMEM: double-buffered Ahi/Alo/Bhi/Blo, 128 x (32+8pad) bf16 each.
// MODE 0: A=hs, B=[Wq|Wk|Wv|Wl_in] by n-block, C=g_qkvl
// MODE 1: A=g_Act, B=Wo (k<2048) / Wl_out (k>=2048), C=out
// ---------------------------------------------------------------------------
#define SPAD      40                        // bf16 elems per row (32 + 8 pad)
#define TBYTES    (128 * SPAD * 2)          // 10240 B per tile
#define STAGE     (4 * TBYTES)              // 40960 B
#define GEMM_SMEM (2 * STAGE)               // 81920 B

template <int MODE>
__global__ __launch_bounds__(256, 1)
void tc_gemm(const float* __restrict__ A,
             const float* __restrict__ B0, const float* __restrict__ B1,
             const float* __restrict__ B2, const float* __restrict__ B3,
             float* __restrict__ C)
{
    constexpr int LDA = (MODE == 0) ? HID : ACTN;
    constexpr int LDC = (MODE == 0) ? QKVLN : HID;
    constexpr int KT  = (MODE == 0) ? HID : ACTN;
    constexpr int NCH = KT / 32;

    extern __shared__ __align__(16) char sm[];

    const int n0  = blockIdx.x * 128;
    const int m0  = blockIdx.y * 128;
    const int tid = threadIdx.x;
    const int wid = tid >> 5;
    const int lane = tid & 31;
    const int wm = wid >> 2;       // 0..1 -> m offset wm*64
    const int wn = wid & 3;        // 0..3 -> n offset wn*32

    const float* Aeff = (MODE == 0) ? A : g_Act;
    float*       Ceff = (MODE == 0) ? g_qkvl : C;

    const float* BsegM0 = nullptr;
    if (MODE == 0) {
        if (n0 < HID)             BsegM0 = B0 + (size_t)n0 * HID;
        else if (n0 < HID + 512)  BsegM0 = B1 + (size_t)(n0 - HID) * HID;
        else if (n0 < HID + 1024) BsegM0 = B2 + (size_t)(n0 - HID - 512) * HID;
        else                      BsegM0 = B3 + (size_t)(n0 - HID - 1024) * HID;
    }

    // Register staging: 4 float4 of A + 4 of B per thread per K-chunk
    float4 ra[4], rb[4];
    auto load_chunk = [&](int k0) {
#pragma unroll
        for (int t = 0; t < 4; t++) {
            const int g = tid + t * 256;        // float4 slot, 1024 total
            const int row = g >> 3, c4 = g & 7; // 8 float4 per 32-col row
            ra[t] = *(const float4*)(Aeff + (size_t)(m0 + row) * LDA + k0 + c4 * 4);
            const float* bp;
            if (MODE == 0) {
                bp = BsegM0 + (size_t)row * HID + k0 + c4 * 4;
            } else {
                if (k0 < HID) bp = B0 + (size_t)(n0 + row) * HID + k0 + c4 * 4;
                else          bp = B1 + (size_t)(n0 + row) * LAT + (k0 - HID) + c4 * 4;
            }
            rb[t] = *(const float4*)bp;
        }
    };

    float acc[4][4][4];
#pragma unroll
    for (int i = 0; i < 4; i++)
#pragma unroll
        for (int j = 0; j < 4; j++)
#pragma unroll
            for (int k = 0; k < 4; k++) acc[i][j][k] = 0.f;

    load_chunk(0);

    const uint32_t smb = smem_u32(sm);

    for (int ch = 0; ch < NCH; ch++) {
        char* buf = sm + (ch & 1) * STAGE;
        char* sAh = buf;
        char* sAl = buf + TBYTES;
        char* sBh = buf + 2 * TBYTES;
        char* sBl = buf + 3 * TBYTES;

        // convert fp32 -> bf16 hi/lo, store padded layout
#pragma unroll
        for (int t = 0; t < 4; t++) {
            const int g = tid + t * 256;
            const int row = g >> 3, c4 = g & 7;
            const uint32_t off = (uint32_t)(row * SPAD + c4 * 4) * 2;  // bytes
            float4 a = ra[t], b = rb[t];
            float ahx = __bfloat162float(__float2bfloat16(a.x));
            float ahy = __bfloat162float(__float2bfloat16(a.y));
            float ahz = __bfloat162float(__float2bfloat16(a.z));
            float ahw = __bfloat162float(__float2bfloat16(a.w));
            float bhx = __bfloat162float(__float2bfloat16(b.x));
            float bhy = __bfloat162float(__float2bfloat16(b.y));
            float bhz = __bfloat162float(__float2bfloat16(b.z));
            float bhw = __bfloat162float(__float2bfloat16(b.w));
            *(uint2*)(sAh + off) = make_uint2(pack_bf16(ahx, ahy), pack_bf16(ahz, ahw));
            *(uint2*)(sAl + off) = make_uint2(pack_bf16(a.x - ahx, a.y - ahy),
                                              pack_bf16(a.z - ahz, a.w - ahw));
            *(uint2*)(sBh + off) = make_uint2(pack_bf16(bhx, bhy), pack_bf16(bhz, bhw));
            *(uint2*)(sBl + off) = make_uint2(pack_bf16(b.x - bhx, b.y - bhy),
                                              pack_bf16(b.z - bhz, b.w - bhw));
        }
        __syncthreads();

        if (ch + 1 < NCH) load_chunk((ch + 1) * 32);  // overlap LDG with MMA

        const uint32_t bb = smb + (uint32_t)(ch & 1) * STAGE;
        const uint32_t aAh = bb;
        const uint32_t aAl = bb + TBYTES;
        const uint32_t aBh = bb + 2 * TBYTES;
        const uint32_t aBl = bb + 3 * TBYTES;

        // ldmatrix lane address components
        const int arow = lane & 15;            // m (A) / n (B) within 16
        const int acol = (lane >> 4) << 3;     // +0 / +8 in k
        const int brow = (lane & 7) + ((lane >> 4) << 3);  // n within 16
        const int bcol = ((lane >> 3) & 1) << 3;           // +0 / +8 in k

#pragma unroll
        for (int ks = 0; ks < 2; ks++) {
            const int k0 = ks * 16;
            uint32_t ah[4][4], al[4][4], bh[4][2], bl[4][2];
#pragma unroll
            for (int mt = 0; mt < 4; mt++) {
                const uint32_t o =
                    (uint32_t)((wm * 64 + mt * 16 + arow) * SPAD + k0 + acol) * 2;
                ldm_x4(ah[mt][0], ah[mt][1], ah[mt][2], ah[mt][3], aAh + o);
                ldm_x4(al[mt][0], al[mt][1], al[mt][2], al[mt][3], aAl + o);
            }
#pragma unroll
            for (int np = 0; np < 2; np++) {   // 2 n-tiles per x4
                const uint32_t o =
                    (uint32_t)((wn * 32 + np * 16 + brow) * SPAD + k0 + bcol) * 2;
                ldm_x4(bh[np * 2][0], bh[np * 2][1], bh[np * 2 + 1][0], bh[np * 2 + 1][1],
                       aBh + o);
                ldm_x4(bl[np * 2][0], bl[np * 2][1], bl[np * 2 + 1][0], bl[np * 2 + 1][1],
                       aBl + o);
            }
#pragma unroll
            for (int mt = 0; mt < 4; mt++)
#pragma unroll
                for (int nt = 0; nt < 4; nt++) {
                    mma16816(acc[mt][nt], ah[mt], bh[nt]);
                    mma16816(acc[mt][nt], ah[mt], bl[nt]);
                    mma16816(acc[mt][nt], al[mt], bh[nt]);
                }
        }
        __syncthreads();
    }

    // Epilogue: fp32 direct stores
#pragma unroll
    for (int mt = 0; mt < 4; mt++) {
        const int r = m0 + wm * 64 + mt * 16 + (lane >> 2);
#pragma unroll
        for (int nt = 0; nt < 4; nt++) {
            const int c = n0 + wn * 32 + nt * 8 + (lane & 3) * 2;
            *(float2*)(Ceff + (size_t)r * LDC + c) =
                make_float2(acc[mt][nt][0], acc[mt][nt][1]);
            *(float2*)(Ceff + (size_t)(r + 8) * LDC + c) =
                make_float2(acc[mt][nt][2], acc[mt][nt][3]);
        }
    }
}

// ---------------------------------------------------------------------------
// RoPE + repack: g_qkvl -> g_Q/g_K/g_V, gate*mid -> Act tail
// ---------------------------------------------------------------------------
__global__ __launch_bounds__(256)
void repack_rope(const float* __restrict__ cosb, const float* __restrict__ sinb,
                 const float* __restrict__ gate)
{
    const int idx = blockIdx.x * 256 + threadIdx.x;
    const int row = idx / QKVLN;
    const int n   = idx - row * QKVLN;
    const int b   = row >> 11;
    const int s   = row & 2047;
    const float v = g_qkvl[idx];

    if (n < HID) {
        const int head = n >> 7, d = n & 127;
        const float c = cosb[s * HD + d], sn = sinb[s * HD + d];
        const float other = (d < 64) ? -g_qkvl[idx + 64] : g_qkvl[idx - 64];
        g_Q[(((size_t)b * NH + head) * SLEN + s) * HD + d] = v * c + other * sn;
    } else if (n < HID + 512) {
        const int nn = n - HID, head = nn >> 7, d = nn & 127;
        const float c = cosb[s * HD + d], sn = sinb[s * HD + d];
        const float other = (d < 64) ? -g_qkvl[idx + 64] : g_qkvl[idx - 64];
        g_K[(((size_t)b * NKV + head) * SLEN + s) * HD + d] = v * c + other * sn;
    } else if (n < HID + 1024) {
        const int nn = n - HID - 512, head = nn >> 7, d = nn & 127;
        g_V[(((size_t)b * NKV + head) * SLEN + s) * HD + d] = v;
    } else {
        g_Act[(size_t)row * ACTN + HID + (n - HID - 1024)] = gate[0] * v;
    }
}

// ---------------------------------------------------------------------------
// Flash attention (fp32 SIMT): 64x64x128 tiles, causal skip.
// ---------------------------------------------------------------------------
#define ATTN_SMEM ((2 * 128 * 68 + 64 * 132 + 64 * 68) * 4)

__global__ __launch_bounds__(256)
void attn_kernel()
{
    extern __shared__ float smf[];
    float* Qs = smf;
    float* Ks = smf + 128 * 68;
    float* Vs = smf + 2 * 128 * 68;
    float* Ps = Vs + 64 * 132;

    const int qt  = (int)gridDim.x - 1 - (int)blockIdx.x;
    const int bh  = blockIdx.y;
    const int b   = bh >> 4;
    const int h   = bh & 15;
    const int kvh = h >> 2;
    const int tid = threadIdx.x;
    const int tx  = tid & 15;
    const int ty  = tid >> 4;

    const float scale = 0.088388347648318447f;

    const float* Qg = g_Q + ((size_t)(b * NH + h) * SLEN + qt * 64) * HD;
    const float* Kg = g_K + (size_t)(b * NKV + kvh) * SLEN * HD;
    const float* Vg = g_V + (size_t)(b * NKV + kvh) * SLEN * HD;

#pragma unroll
    for (int i = tid; i < 64 * 32; i += 256) {
        const int r = i >> 5, c4 = (i & 31) << 2;
        float4 qv = *(const float4*)(Qg + r * HD + c4);
        Qs[(c4 + 0) * 68 + r] = qv.x * scale;
        Qs[(c4 + 1) * 68 + r] = qv.y * scale;
        Qs[(c4 + 2) * 68 + r] = qv.z * scale;
        Qs[(c4 + 3) * 68 + r] = qv.w * scale;
    }

    float acc[4][8];
    float rmax[4], rsum[4];
#pragma unroll
    for (int i = 0; i < 4; i++) {
        rmax[i] = -CUDART_INF_F; rsum[i] = 0.f;
#pragma unroll
        for (int j = 0; j < 8; j++) acc[i][j] = 0.f;
    }

    const int ntiles = qt + 1;
    for (int kt = 0; kt < ntiles; kt++) {
        const float* Kt = Kg + (size_t)kt * 64 * HD;
        const float* Vt = Vg + (size_t)kt * 64 * HD;

        __syncthreads();
#pragma unroll
        for (int i = tid; i < 64 * 32; i += 256) {
            const int r = i >> 5, c4 = (i & 31) << 2;
            float4 kv = *(const float4*)(Kt + r * HD + c4);
            Ks[(c4 + 0) * 68 + r] = kv.x;
            Ks[(c4 + 1) * 68 + r] = kv.y;
            Ks[(c4 + 2) * 68 + r] = kv.z;
            Ks[(c4 + 3) * 68 + r] = kv.w;
            *(float4*)(Vs + r * 132 + c4) = *(const float4*)(Vt + r * HD + c4);
        }
        __syncthreads();

        float s[4][4];
#pragma unroll
        for (int i = 0; i < 4; i++)
#pragma unroll
            for (int j = 0; j < 4; j++) s[i][j] = 0.f;

#pragma unroll 8
        for (int d = 0; d < 128; d++) {
            float4 qa = *(const float4*)(Qs + d * 68 + ty * 4);
            float4 kb = *(const float4*)(Ks + d * 68 + tx * 4);
            const float qr[4] = {qa.x, qa.y, qa.z, qa.w};
            const float kr[4] = {kb.x, kb.y, kb.z, kb.w};
#pragma unroll
            for (int i = 0; i < 4; i++)
#pragma unroll
                for (int j = 0; j < 4; j++)
                    s[i][j] = fmaf(qr[i], kr[j], s[i][j]);
        }

        if (kt == qt) {
#pragma unroll
            for (int i = 0; i < 4; i++)
#pragma unroll
                for (int j = 0; j < 4; j++)
                    if (tx * 4 + j > ty * 4 + i) s[i][j] = -CUDART_INF_F;
        }

#pragma unroll
        for (int i = 0; i < 4; i++) {
            float mx = fmaxf(fmaxf(s[i][0], s[i][1]), fmaxf(s[i][2], s[i][3]));
#pragma unroll
            for (int o = 8; o > 0; o >>= 1)
                mx = fmaxf(mx, __shfl_xor_sync(0xffffffffu, mx, o));
            const float mnew = fmaxf(rmax[i], mx);
            const float corr = __expf(rmax[i] - mnew);
            rmax[i] = mnew;
            float psum = 0.f;
#pragma unroll
            for (int j = 0; j < 4; j++) {
                const float p = __expf(s[i][j] - mnew);
                s[i][j] = p; psum += p;
            }
            rsum[i] = rsum[i] * corr + psum;
#pragma unroll
            for (int j = 0; j < 8; j++) acc[i][j] *= corr;
            *(float4*)(Ps + (ty * 4 + i) * 68 + tx * 4) =
                make_float4(s[i][0], s[i][1], s[i][2], s[i][3]);
        }
        __syncthreads();

#pragma unroll 8
        for (int n = 0; n < 64; n++) {
            const float pp[4] = {Ps[(ty * 4 + 0) * 68 + n], Ps[(ty * 4 + 1) * 68 + n],
                                 Ps[(ty * 4 + 2) * 68 + n], Ps[(ty * 4 + 3) * 68 + n]};
            float4 va = *(const float4*)(Vs + n * 132 + tx * 4);
            float4 vb = *(const float4*)(Vs + n * 132 + 64 + tx * 4);
            const float vv[8] = {va.x, va.y, va.z, va.w, vb.x, vb.y, vb.z, vb.w};
#pragma unroll
            for (int i = 0; i < 4; i++)
#pragma unroll
                for (int j = 0; j < 8; j++)
                    acc[i][j] = fmaf(pp[i], vv[j], acc[i][j]);
        }
    }

#pragma unroll
    for (int i = 0; i < 4; i++) {
        float sum = rsum[i];
#pragma unroll
        for (int o = 8; o > 0; o >>= 1)
            sum += __shfl_xor_sync(0xffffffffu, sum, o);
        const float inv = 1.f / sum;
        const int m = qt * 64 + ty * 4 + i;
        float* op = g_Act + ((size_t)b * SLEN + m) * ACTN + h * HD;
        *(float4*)(op + tx * 4)      = make_float4(acc[i][0] * inv, acc[i][1] * inv,
                                                   acc[i][2] * inv, acc[i][3] * inv);
        *(float4*)(op + 64 + tx * 4) = make_float4(acc[i][4] * inv, acc[i][5] * inv,
                                                   acc[i][6] * inv, acc[i][7] * inv);
    }
}

// ---------------------------------------------------------------------------
extern "C" void kernel_launch(void* const* d_in, const int* in_sizes, int n_in,
                              void* d_out, int out_size)
{
    const float* hs     = (const float*)d_in[0];
    const float* cosb   = (const float*)d_in[1];
    const float* sinb   = (const float*)d_in[2];
    // d_in[3] = attention_mask (pure causal; implemented directly)
    const float* Wq     = (const float*)d_in[4];
    const float* Wk     = (const float*)d_in[5];
    const float* Wv     = (const float*)d_in[6];
    const float* Wo     = (const float*)d_in[7];
    const float* Wl_in  = (const float*)d_in[8];
    const float* Wl_out = (const float*)d_in[9];
    const float* gate   = (const float*)d_in[10];
    float* out = (float*)d_out;

    cudaFuncSetAttribute(attn_kernel,
                         cudaFuncAttributeMaxDynamicSharedMemorySize, ATTN_SMEM);
    cudaFuncSetAttribute(tc_gemm<0>,
                         cudaFuncAttributeMaxDynamicSharedMemorySize, GEMM_SMEM);
    cudaFuncSetAttribute(tc_gemm<1>,
                         cudaFuncAttributeMaxDynamicSharedMemorySize, GEMM_SMEM);

    // 1) fused [Q|K|V|latent_mid] projection (mma.sync bf16 3-pass)
    tc_gemm<0><<<dim3(QKVLN / 128, ROWS / 128), 256, GEMM_SMEM>>>(
        hs, Wq, Wk, Wv, Wl_in, nullptr);
    // 2) RoPE + repack (+ gate*mid into Act tail)
    repack_rope<<<(ROWS * QKVLN) / 256, 256>>>(cosb, sinb, gate);
    // 3) flash attention -> Act[:, 0:2048]
    attn_kernel<<<dim3(SLEN / 64, BATCH * NH), 256, ATTN_SMEM>>>();
    // 4) out = Act @ [Wo | Wl_out]^T (mma.sync bf16 3-pass)
    tc_gemm<1><<<dim3(HID / 128, ROWS / 128), 256, GEMM_SMEM>>>(
        nullptr, Wo, Wl_out, nullptr, nullptr, out);
}

// round 4
// speedup vs baseline: 3.0214x; 1.9817x over previous
#include <cuda_runtime.h>
#include <cuda_bf16.h>
#include <cuda_fp16.h>
#include <math_constants.h>
#include <cstdint>

#define BATCH 2
#define SLEN  2048
#define HID   2048
#define NH    16
#define NKV   4
#define HD    128
#define LAT   256
#define ROWS  (BATCH * SLEN)          // 4096
#define QKVLN (HID + 512 + 512 + LAT) // 3328
#define ACTN  (HID + LAT)             // 2304

// Scratch (static device globals: allocation-free per harness rules)
__device__ float  g_qkvl[(size_t)ROWS * QKVLN];
__device__ __half g_Qh[(size_t)BATCH * NH * SLEN * HD];   // fp16, pre-scaled
__device__ __half g_Kh[(size_t)BATCH * NKV * SLEN * HD];
__device__ __half g_Vh[(size_t)BATCH * NKV * SLEN * HD];
__device__ float  g_Act[(size_t)ROWS * ACTN];

// ---------------------------------------------------------------------------
// mma.sync helpers (base sm_103-legal: no tcgen05)
// ---------------------------------------------------------------------------
__device__ __forceinline__ uint32_t smem_u32(const void* p) {
    uint32_t a;
    asm("{ .reg .u64 t; cvta.to.shared.u64 t, %1; cvt.u32.u64 %0, t; }"
        : "=r"(a) : "l"(p));
    return a;
}
__device__ __forceinline__ void ldm_x4(uint32_t& r0, uint32_t& r1,
                                       uint32_t& r2, uint32_t& r3, uint32_t addr) {
    asm volatile("ldmatrix.sync.aligned.m8n8.x4.shared.b16 {%0,%1,%2,%3}, [%4];"
                 : "=r"(r0), "=r"(r1), "=r"(r2), "=r"(r3) : "r"(addr));
}
__device__ __forceinline__ void ldm_x4t(uint32_t& r0, uint32_t& r1,
                                        uint32_t& r2, uint32_t& r3, uint32_t addr) {
    asm volatile("ldmatrix.sync.aligned.m8n8.x4.trans.shared.b16 {%0,%1,%2,%3}, [%4];"
                 : "=r"(r0), "=r"(r1), "=r"(r2), "=r"(r3) : "r"(addr));
}
__device__ __forceinline__ void mma16816(float* c, const uint32_t* a, const uint32_t* b) {
    asm volatile(
        "mma.sync.aligned.m16n8k16.row.col.f32.bf16.bf16.f32 "
        "{%0,%1,%2,%3}, {%4,%5,%6,%7}, {%8,%9}, {%0,%1,%2,%3};"
        : "+f"(c[0]), "+f"(c[1]), "+f"(c[2]), "+f"(c[3])
        : "r"(a[0]), "r"(a[1]), "r"(a[2]), "r"(a[3]), "r"(b[0]), "r"(b[1]));
}
__device__ __forceinline__ void mma16816h(float* c, const uint32_t* a, const uint32_t* b) {
    asm volatile(
        "mma.sync.aligned.m16n8k16.row.col.f32.f16.f16.f32 "
        "{%0,%1,%2,%3}, {%4,%5,%6,%7}, {%8,%9}, {%0,%1,%2,%3};"
        : "+f"(c[0]), "+f"(c[1]), "+f"(c[2]), "+f"(c[3])
        : "r"(a[0]), "r"(a[1]), "r"(a[2]), "r"(a[3]), "r"(b[0]), "r"(b[1]));
}
__device__ __forceinline__ uint32_t pack_bf16(float lo, float hi) {
    uint32_t r;
    asm("cvt.rn.bf16x2.f32 %0, %1, %2;" : "=r"(r) : "f"(hi), "f"(lo));
    return r;
}
__device__ __forceinline__ uint32_t pack_f16(float lo, float hi) {
    uint32_t r;
    asm("cvt.rn.f16x2.f32 %0, %1, %2;" : "=r"(r) : "f"(hi), "f"(lo));
    return r;
}

// ---------------------------------------------------------------------------
// bf16 split-precision NT GEMM on mma.sync (unchanged from R3; err ~1e-5)
// ---------------------------------------------------------------------------
#define SPAD      40
#define TBYTES    (128 * SPAD * 2)
#define STAGE     (4 * TBYTES)
#define GEMM_SMEM (2 * STAGE)

template <int MODE>
__global__ __launch_bounds__(256, 1)
void tc_gemm(const float* __restrict__ A,
             const float* __restrict__ B0, const float* __restrict__ B1,
             const float* __restrict__ B2, const float* __restrict__ B3,
             float* __restrict__ C)
{
    constexpr int LDA = (MODE == 0) ? HID : ACTN;
    constexpr int LDC = (MODE == 0) ? QKVLN : HID;
    constexpr int KT  = (MODE == 0) ? HID : ACTN;
    constexpr int NCH = KT / 32;

    extern __shared__ __align__(16) char sm[];

    const int n0  = blockIdx.x * 128;
    const int m0  = blockIdx.y * 128;
    const int tid = threadIdx.x;
    const int wid = tid >> 5;
    const int lane = tid & 31;
    const int wm = wid >> 2;
    const int wn = wid & 3;

    const float* Aeff = (MODE == 0) ? A : g_Act;
    float*       Ceff = (MODE == 0) ? g_qkvl : C;

    const float* BsegM0 = nullptr;
    if (MODE == 0) {
        if (n0 < HID)             BsegM0 = B0 + (size_t)n0 * HID;
        else if (n0 < HID + 512)  BsegM0 = B1 + (size_t)(n0 - HID) * HID;
        else if (n0 < HID + 1024) BsegM0 = B2 + (size_t)(n0 - HID - 512) * HID;
        else                      BsegM0 = B3 + (size_t)(n0 - HID - 1024) * HID;
    }

    float4 ra[4], rb[4];
    auto load_chunk = [&](int k0) {
#pragma unroll
        for (int t = 0; t < 4; t++) {
            const int g = tid + t * 256;
            const int row = g >> 3, c4 = g & 7;
            ra[t] = *(const float4*)(Aeff + (size_t)(m0 + row) * LDA + k0 + c4 * 4);
            const float* bp;
            if (MODE == 0) {
                bp = BsegM0 + (size_t)row * HID + k0 + c4 * 4;
            } else {
                if (k0 < HID) bp = B0 + (size_t)(n0 + row) * HID + k0 + c4 * 4;
                else          bp = B1 + (size_t)(n0 + row) * LAT + (k0 - HID) + c4 * 4;
            }
            rb[t] = *(const float4*)bp;
        }
    };

    float acc[4][4][4];
#pragma unroll
    for (int i = 0; i < 4; i++)
#pragma unroll
        for (int j = 0; j < 4; j++)
#pragma unroll
            for (int k = 0; k < 4; k++) acc[i][j][k] = 0.f;

    load_chunk(0);

    const uint32_t smb = smem_u32(sm);

    for (int ch = 0; ch < NCH; ch++) {
        char* buf = sm + (ch & 1) * STAGE;
        char* sAh = buf;
        char* sAl = buf + TBYTES;
        char* sBh = buf + 2 * TBYTES;
        char* sBl = buf + 3 * TBYTES;

#pragma unroll
        for (int t = 0; t < 4; t++) {
            const int g = tid + t * 256;
            const int row = g >> 3, c4 = g & 7;
            const uint32_t off = (uint32_t)(row * SPAD + c4 * 4) * 2;
            float4 a = ra[t], b = rb[t];
            float ahx = __bfloat162float(__float2bfloat16(a.x));
            float ahy = __bfloat162float(__float2bfloat16(a.y));
            float ahz = __bfloat162float(__float2bfloat16(a.z));
            float ahw = __bfloat162float(__float2bfloat16(a.w));
            float bhx = __bfloat162float(__float2bfloat16(b.x));
            float bhy = __bfloat162float(__float2bfloat16(b.y));
            float bhz = __bfloat162float(__float2bfloat16(b.z));
            float bhw = __bfloat162float(__float2bfloat16(b.w));
            *(uint2*)(sAh + off) = make_uint2(pack_bf16(ahx, ahy), pack_bf16(ahz, ahw));
            *(uint2*)(sAl + off) = make_uint2(pack_bf16(a.x - ahx, a.y - ahy),
                                              pack_bf16(a.z - ahz, a.w - ahw));
            *(uint2*)(sBh + off) = make_uint2(pack_bf16(bhx, bhy), pack_bf16(bhz, bhw));
            *(uint2*)(sBl + off) = make_uint2(pack_bf16(b.x - bhx, b.y - bhy),
                                              pack_bf16(b.z - bhz, b.w - bhw));
        }
        __syncthreads();

        if (ch + 1 < NCH) load_chunk((ch + 1) * 32);

        const uint32_t bb = smb + (uint32_t)(ch & 1) * STAGE;
        const uint32_t aAh = bb;
        const uint32_t aAl = bb + TBYTES;
        const uint32_t aBh = bb + 2 * TBYTES;
        const uint32_t aBl = bb + 3 * TBYTES;

        const int arow = lane & 15;
        const int acol = (lane >> 4) << 3;
        const int brow = (lane & 7) + ((lane >> 4) << 3);
        const int bcol = ((lane >> 3) & 1) << 3;

#pragma unroll
        for (int ks = 0; ks < 2; ks++) {
            const int k0 = ks * 16;
            uint32_t ah[4][4], al[4][4], bh[4][2], bl[4][2];
#pragma unroll
            for (int mt = 0; mt < 4; mt++) {
                const uint32_t o =
                    (uint32_t)((wm * 64 + mt * 16 + arow) * SPAD + k0 + acol) * 2;
                ldm_x4(ah[mt][0], ah[mt][1], ah[mt][2], ah[mt][3], aAh + o);
                ldm_x4(al[mt][0], al[mt][1], al[mt][2], al[mt][3], aAl + o);
            }
#pragma unroll
            for (int np = 0; np < 2; np++) {
                const uint32_t o =
                    (uint32_t)((wn * 32 + np * 16 + brow) * SPAD + k0 + bcol) * 2;
                ldm_x4(bh[np * 2][0], bh[np * 2][1], bh[np * 2 + 1][0], bh[np * 2 + 1][1],
                       aBh + o);
                ldm_x4(bl[np * 2][0], bl[np * 2][1], bl[np * 2 + 1][0], bl[np * 2 + 1][1],
                       aBl + o);
            }
#pragma unroll
            for (int mt = 0; mt < 4; mt++)
#pragma unroll
                for (int nt = 0; nt < 4; nt++) {
                    mma16816(acc[mt][nt], ah[mt], bh[nt]);
                    mma16816(acc[mt][nt], ah[mt], bl[nt]);
                    mma16816(acc[mt][nt], al[mt], bh[nt]);
                }
        }
        __syncthreads();
    }

#pragma unroll
    for (int mt = 0; mt < 4; mt++) {
        const int r = m0 + wm * 64 + mt * 16 + (lane >> 2);
#pragma unroll
        for (int nt = 0; nt < 4; nt++) {
            const int c = n0 + wn * 32 + nt * 8 + (lane & 3) * 2;
            *(float2*)(Ceff + (size_t)r * LDC + c) =
                make_float2(acc[mt][nt][0], acc[mt][nt][1]);
            *(float2*)(Ceff + (size_t)(r + 8) * LDC + c) =
                make_float2(acc[mt][nt][2], acc[mt][nt][3]);
        }
    }
}

// ---------------------------------------------------------------------------
// RoPE + repack: g_qkvl -> fp16 Q (pre-scaled) / K / V, gate*mid -> Act tail
// ---------------------------------------------------------------------------
__global__ __launch_bounds__(256)
void repack_rope(const float* __restrict__ cosb, const float* __restrict__ sinb,
                 const float* __restrict__ gate)
{
    const int idx = blockIdx.x * 256 + threadIdx.x;
    const int row = idx / QKVLN;
    const int n   = idx - row * QKVLN;
    const int b   = row >> 11;
    const int s   = row & 2047;
    const float v = g_qkvl[idx];
    const float scale = 0.088388347648318447f;  // 1/sqrt(128)

    if (n < HID) {
        const int head = n >> 7, d = n & 127;
        const float c = cosb[s * HD + d], sn = sinb[s * HD + d];
        const float other = (d < 64) ? -g_qkvl[idx + 64] : g_qkvl[idx - 64];
        g_Qh[(((size_t)b * NH + head) * SLEN + s) * HD + d] =
            __float2half((v * c + other * sn) * scale);
    } else if (n < HID + 512) {
        const int nn = n - HID, head = nn >> 7, d = nn & 127;
        const float c = cosb[s * HD + d], sn = sinb[s * HD + d];
        const float other = (d < 64) ? -g_qkvl[idx + 64] : g_qkvl[idx - 64];
        g_Kh[(((size_t)b * NKV + head) * SLEN + s) * HD + d] =
            __float2half(v * c + other * sn);
    } else if (n < HID + 1024) {
        const int nn = n - HID - 512, head = nn >> 7, d = nn & 127;
        g_Vh[(((size_t)b * NKV + head) * SLEN + s) * HD + d] = __float2half(v);
    } else {
        g_Act[(size_t)row * ACTN + HID + (n - HID - 1024)] = gate[0] * v;
    }
}

// ---------------------------------------------------------------------------
// Flash attention on mma.sync fp16 (exact products, fp32 accum).
// CTA: 128 q-rows, 8 warps (m16 each), k-blocks of 64, causal skip.
// ---------------------------------------------------------------------------
#define LDT 136
#define ATTN_SMEM ((128 * LDT + 64 * LDT + 64 * LDT) * 2)  // 69632 B

__global__ __launch_bounds__(256, 1)
void attn_kernel()
{
    extern __shared__ __half smh[];
    __half* Qs = smh;                 // [128][LDT]
    __half* Ks = smh + 128 * LDT;     // [64][LDT]
    __half* Vs = Ks + 64 * LDT;       // [64][LDT]

    const int qt  = (int)gridDim.x - 1 - (int)blockIdx.x;  // long blocks first
    const int bh  = blockIdx.y;
    const int b   = bh >> 4;
    const int h   = bh & 15;
    const int kvh = h >> 2;
    const int tid = threadIdx.x;
    const int wid = tid >> 5;
    const int lane = tid & 31;

    const __half* Qg = g_Qh + ((size_t)(b * NH + h) * SLEN + qt * 128) * HD;
    const __half* Kg = g_Kh + (size_t)(b * NKV + kvh) * SLEN * HD;
    const __half* Vg = g_Vh + (size_t)(b * NKV + kvh) * SLEN * HD;

    // stage Q tile (128x128 fp16)
#pragma unroll
    for (int i = 0; i < 8; i++) {
        const int g = tid + i * 256;
        const int row = g >> 4, c8 = (g & 15) * 8;
        *(uint4*)(Qs + row * LDT + c8) = *(const uint4*)(Qg + row * HD + c8);
    }
    __syncthreads();

    // Q A-frags in registers (reused across all k-blocks)
    uint32_t qf[8][4];
    {
        const uint32_t qb = smem_u32(Qs) +
            (uint32_t)((wid * 16 + (lane & 15)) * LDT + ((lane >> 4) << 3)) * 2;
#pragma unroll
        for (int ks = 0; ks < 8; ks++)
            ldm_x4(qf[ks][0], qf[ks][1], qf[ks][2], qf[ks][3], qb + ks * 32);
    }

    float acc[16][4];
#pragma unroll
    for (int i = 0; i < 16; i++)
#pragma unroll
        for (int j = 0; j < 4; j++) acc[i][j] = 0.f;
    float rmax[2] = {-CUDART_INF_F, -CUDART_INF_F};
    float rsum[2] = {0.f, 0.f};

    const uint32_t kbase_a = smem_u32(Ks) +
        (uint32_t)(((lane & 7) + ((lane >> 4) << 3)) * LDT + (((lane >> 3) & 1) << 3)) * 2;
    const uint32_t vbase_a = smem_u32(Vs) +
        (uint32_t)((lane & 15) * LDT + ((lane >> 4) << 3)) * 2;

    const int nblocks = 2 * qt + 2;
    for (int kb = 0; kb < nblocks; kb++) {
        __syncthreads();
        const __half* Kt = Kg + (size_t)kb * 64 * HD;
        const __half* Vt = Vg + (size_t)kb * 64 * HD;
#pragma unroll
        for (int i = 0; i < 4; i++) {
            const int g = tid + i * 256;
            const int row = g >> 4, c8 = (g & 15) * 8;
            *(uint4*)(Ks + row * LDT + c8) = *(const uint4*)(Kt + row * HD + c8);
            *(uint4*)(Vs + row * LDT + c8) = *(const uint4*)(Vt + row * HD + c8);
        }
        __syncthreads();

        // ---- S = Q K^T ----
        float s[8][4];
#pragma unroll
        for (int i = 0; i < 8; i++)
#pragma unroll
            for (int j = 0; j < 4; j++) s[i][j] = 0.f;

#pragma unroll
        for (int ks = 0; ks < 8; ks++) {
#pragma unroll
            for (int np = 0; np < 4; np++) {
                uint32_t k0, k1, k2, k3;
                ldm_x4(k0, k1, k2, k3,
                       kbase_a + (uint32_t)(np * 16 * LDT + ks * 16) * 2);
                uint32_t bA[2] = {k0, k1}, bB[2] = {k2, k3};
                mma16816h(s[np * 2],     qf[ks], bA);
                mma16816h(s[np * 2 + 1], qf[ks], bB);
            }
        }

        // ---- causal mask on diagonal-region blocks ----
        if (kb >= 2 * qt) {
            const int kc = kb * 64 + (lane & 3) * 2;
            const int mr = qt * 128 + wid * 16 + (lane >> 2);
#pragma unroll
            for (int nt = 0; nt < 8; nt++) {
                const int c = kc + nt * 8;
                if (c > mr)         s[nt][0] = -CUDART_INF_F;
                if (c + 1 > mr)     s[nt][1] = -CUDART_INF_F;
                if (c > mr + 8)     s[nt][2] = -CUDART_INF_F;
                if (c + 1 > mr + 8) s[nt][3] = -CUDART_INF_F;
            }
        }

        // ---- online softmax (rows r and r+8; 4-lane groups share a row) ----
#pragma unroll
        for (int hf = 0; hf < 2; hf++) {
            float mx = -CUDART_INF_F;
#pragma unroll
            for (int nt = 0; nt < 8; nt++)
                mx = fmaxf(mx, fmaxf(s[nt][2 * hf], s[nt][2 * hf + 1]));
            mx = fmaxf(mx, __shfl_xor_sync(0xffffffffu, mx, 1));
            mx = fmaxf(mx, __shfl_xor_sync(0xffffffffu, mx, 2));
            const float mnew = fmaxf(rmax[hf], mx);
            const float corr = __expf(rmax[hf] - mnew);
            rmax[hf] = mnew;
            float ps = 0.f;
#pragma unroll
            for (int nt = 0; nt < 8; nt++) {
                const float p0 = __expf(s[nt][2 * hf] - mnew);
                const float p1 = __expf(s[nt][2 * hf + 1] - mnew);
                s[nt][2 * hf] = p0; s[nt][2 * hf + 1] = p1;
                ps += p0 + p1;
            }
            ps += __shfl_xor_sync(0xffffffffu, ps, 1);
            ps += __shfl_xor_sync(0xffffffffu, ps, 2);
            rsum[hf] = rsum[hf] * corr + ps;
#pragma unroll
            for (int nt = 0; nt < 16; nt++) {
                acc[nt][2 * hf]     *= corr;
                acc[nt][2 * hf + 1] *= corr;
            }
        }

        // ---- pack P into fp16 A-frags ----
        uint32_t pa[4][4];
#pragma unroll
        for (int kt = 0; kt < 4; kt++) {
            pa[kt][0] = pack_f16(s[2 * kt][0],     s[2 * kt][1]);
            pa[kt][1] = pack_f16(s[2 * kt][2],     s[2 * kt][3]);
            pa[kt][2] = pack_f16(s[2 * kt + 1][0], s[2 * kt + 1][1]);
            pa[kt][3] = pack_f16(s[2 * kt + 1][2], s[2 * kt + 1][3]);
        }

        // ---- ctx += P V  (V B-frags via ldmatrix.trans) ----
#pragma unroll
        for (int np = 0; np < 8; np++) {
#pragma unroll
            for (int kt = 0; kt < 4; kt++) {
                uint32_t v0, v1, v2, v3;
                ldm_x4t(v0, v1, v2, v3,
                        vbase_a + (uint32_t)(kt * 16 * LDT + np * 16) * 2);
                uint32_t bA[2] = {v0, v1}, bB[2] = {v2, v3};
                mma16816h(acc[np * 2],     pa[kt], bA);
                mma16816h(acc[np * 2 + 1], pa[kt], bB);
            }
        }
    }

    // ---- epilogue ----
    const float inv0 = 1.f / rsum[0];
    const float inv1 = 1.f / rsum[1];
    const int mr = qt * 128 + wid * 16 + (lane >> 2);
    float* op = g_Act + ((size_t)b * SLEN + mr) * ACTN + h * HD;
#pragma unroll
    for (int nt = 0; nt < 16; nt++) {
        const int c = nt * 8 + (lane & 3) * 2;
        *(float2*)(op + c) = make_float2(acc[nt][0] * inv0, acc[nt][1] * inv0);
        *(float2*)(op + (size_t)8 * ACTN + c) =
            make_float2(acc[nt][2] * inv1, acc[nt][3] * inv1);
    }
}

// ---------------------------------------------------------------------------
extern "C" void kernel_launch(void* const* d_in, const int* in_sizes, int n_in,
                              void* d_out, int out_size)
{
    const float* hs     = (const float*)d_in[0];
    const float* cosb   = (const float*)d_in[1];
    const float* sinb   = (const float*)d_in[2];
    // d_in[3] = attention_mask (pure causal; implemented directly)
    const float* Wq     = (const float*)d_in[4];
    const float* Wk     = (const float*)d_in[5];
    const float* Wv     = (const float*)d_in[6];
    const float* Wo     = (const float*)d_in[7];
    const float* Wl_in  = (const float*)d_in[8];
    const float* Wl_out = (const float*)d_in[9];
    const float* gate   = (const float*)d_in[10];
    float* out = (float*)d_out;

    cudaFuncSetAttribute(attn_kernel,
                         cudaFuncAttributeMaxDynamicSharedMemorySize, ATTN_SMEM);
    cudaFuncSetAttribute(tc_gemm<0>,
                         cudaFuncAttributeMaxDynamicSharedMemorySize, GEMM_SMEM);
    cudaFuncSetAttribute(tc_gemm<1>,
                         cudaFuncAttributeMaxDynamicSharedMemorySize, GEMM_SMEM);

    // 1) fused [Q|K|V|latent_mid] projection (mma.sync bf16 3-pass)
    tc_gemm<0><<<dim3(QKVLN / 128, ROWS / 128), 256, GEMM_SMEM>>>(
        hs, Wq, Wk, Wv, Wl_in, nullptr);
    // 2) RoPE + repack -> fp16 Q/K/V (+ gate*mid into Act tail)
    repack_rope<<<(ROWS * QKVLN) / 256, 256>>>(cosb, sinb, gate);
    // 3) flash attention (fp16 mma) -> Act[:, 0:2048]
    attn_kernel<<<dim3(SLEN / 128, BATCH * NH), 256, ATTN_SMEM>>>();
    // 4) out = Act @ [Wo | Wl_out]^T (mma.sync bf16 3-pass)
    tc_gemm<1><<<dim3(HID / 128, ROWS / 128), 256, GEMM_SMEM>>>(
        nullptr, Wo, Wl_out, nullptr, nullptr, out);
}

// round 5
// speedup vs baseline: 5.1844x; 1.7159x over previous
#include <cuda_runtime.h>
#include <cuda_bf16.h>
#include <cuda_fp16.h>
#include <math_constants.h>
#include <cstdint>

#define BATCH 2
#define SLEN  2048
#define HID   2048
#define NH    16
#define NKV   4
#define HD    128
#define LAT   256
#define ROWS  (BATCH * SLEN)          // 4096
#define QKVLN (HID + 512 + 512 + LAT) // 3328
#define ACTN  (HID + LAT)             // 2304

// Scratch (static device globals: allocation-free per harness rules)
__device__ float  g_qkvl[(size_t)ROWS * QKVLN];
__device__ __half g_Qh[(size_t)BATCH * NH * SLEN * HD];   // fp16, pre-scaled
__device__ __half g_Kh[(size_t)BATCH * NKV * SLEN * HD];
__device__ __half g_Vh[(size_t)BATCH * NKV * SLEN * HD];
__device__ float  g_Act[(size_t)ROWS * ACTN];

// ---------------------------------------------------------------------------
// mma.sync helpers (base sm_103-legal: no tcgen05)
// ---------------------------------------------------------------------------
__device__ __forceinline__ uint32_t smem_u32(const void* p) {
    uint32_t a;
    asm("{ .reg .u64 t; cvta.to.shared.u64 t, %1; cvt.u32.u64 %0, t; }"
        : "=r"(a) : "l"(p));
    return a;
}
__device__ __forceinline__ void ldm_x4(uint32_t& r0, uint32_t& r1,
                                       uint32_t& r2, uint32_t& r3, uint32_t addr) {
    asm volatile("ldmatrix.sync.aligned.m8n8.x4.shared.b16 {%0,%1,%2,%3}, [%4];"
                 : "=r"(r0), "=r"(r1), "=r"(r2), "=r"(r3) : "r"(addr));
}
__device__ __forceinline__ void ldm_x4t(uint32_t& r0, uint32_t& r1,
                                        uint32_t& r2, uint32_t& r3, uint32_t addr) {
    asm volatile("ldmatrix.sync.aligned.m8n8.x4.trans.shared.b16 {%0,%1,%2,%3}, [%4];"
                 : "=r"(r0), "=r"(r1), "=r"(r2), "=r"(r3) : "r"(addr));
}
__device__ __forceinline__ void mma16816h(float* c, const uint32_t* a, const uint32_t* b) {
    asm volatile(
        "mma.sync.aligned.m16n8k16.row.col.f32.f16.f16.f32 "
        "{%0,%1,%2,%3}, {%4,%5,%6,%7}, {%8,%9}, {%0,%1,%2,%3};"
        : "+f"(c[0]), "+f"(c[1]), "+f"(c[2]), "+f"(c[3])
        : "r"(a[0]), "r"(a[1]), "r"(a[2]), "r"(a[3]), "r"(b[0]), "r"(b[1]));
}
__device__ __forceinline__ uint32_t pack_f16(float lo, float hi) {
    uint32_t r;
    asm("cvt.rn.f16x2.f32 %0, %1, %2;" : "=r"(r) : "f"(hi), "f"(lo));
    return r;
}

// ---------------------------------------------------------------------------
// fp16 single-pass NT GEMM on mma.sync: C[M,N] = A[M,K] * B[N,K]^T (fp32 I/O)
// 128x128 CTA tile, BK=32, 8 warps (2x4), warp tile 64x32 (4x4 m16n8k16).
// fp16 products exact into fp32 accum; only input rounding error (~2.3e-4).
// SMEM: double-buffered A/B fp16 tiles, 128 x (32+8pad). 2 CTAs/SM.
// MODE 0: A=hs, B=[Wq|Wk|Wv|Wl_in] by n-block, C=g_qkvl
// MODE 1: A=g_Act, B=Wo (k<2048) / Wl_out (k>=2048), C=out
// ---------------------------------------------------------------------------
#define SPAD      40
#define TBYTES    (128 * SPAD * 2)          // 10240 B
#define STAGE     (2 * TBYTES)              // 20480 B (A + B)
#define GEMM_SMEM (2 * STAGE)               // 40960 B

template <int MODE>
__global__ __launch_bounds__(256, 2)
void tc_gemm(const float* __restrict__ A,
             const float* __restrict__ B0, const float* __restrict__ B1,
             const float* __restrict__ B2, const float* __restrict__ B3,
             float* __restrict__ C)
{
    constexpr int LDA = (MODE == 0) ? HID : ACTN;
    constexpr int LDC = (MODE == 0) ? QKVLN : HID;
    constexpr int KT  = (MODE == 0) ? HID : ACTN;
    constexpr int NCH = KT / 32;

    extern __shared__ __align__(16) char sm[];

    const int n0  = blockIdx.x * 128;
    const int m0  = blockIdx.y * 128;
    const int tid = threadIdx.x;
    const int wid = tid >> 5;
    const int lane = tid & 31;
    const int wm = wid >> 2;
    const int wn = wid & 3;

    const float* Aeff = (MODE == 0) ? A : g_Act;
    float*       Ceff = (MODE == 0) ? g_qkvl : C;

    const float* BsegM0 = nullptr;
    if (MODE == 0) {
        if (n0 < HID)             BsegM0 = B0 + (size_t)n0 * HID;
        else if (n0 < HID + 512)  BsegM0 = B1 + (size_t)(n0 - HID) * HID;
        else if (n0 < HID + 1024) BsegM0 = B2 + (size_t)(n0 - HID - 512) * HID;
        else                      BsegM0 = B3 + (size_t)(n0 - HID - 1024) * HID;
    }

    // staging: convert fp32->fp16x2 at load time (uint2 per float4)
    uint2 rah[4], rbh[4];
    auto load_chunk = [&](int k0) {
#pragma unroll
        for (int t = 0; t < 4; t++) {
            const int g = tid + t * 256;
            const int row = g >> 3, c4 = g & 7;
            float4 a = *(const float4*)(Aeff + (size_t)(m0 + row) * LDA + k0 + c4 * 4);
            const float* bp;
            if (MODE == 0) {
                bp = BsegM0 + (size_t)row * HID + k0 + c4 * 4;
            } else {
                if (k0 < HID) bp = B0 + (size_t)(n0 + row) * HID + k0 + c4 * 4;
                else          bp = B1 + (size_t)(n0 + row) * LAT + (k0 - HID) + c4 * 4;
            }
            float4 b = *(const float4*)bp;
            rah[t] = make_uint2(pack_f16(a.x, a.y), pack_f16(a.z, a.w));
            rbh[t] = make_uint2(pack_f16(b.x, b.y), pack_f16(b.z, b.w));
        }
    };

    float acc[4][4][4];
#pragma unroll
    for (int i = 0; i < 4; i++)
#pragma unroll
        for (int j = 0; j < 4; j++)
#pragma unroll
            for (int k = 0; k < 4; k++) acc[i][j][k] = 0.f;

    load_chunk(0);

    const uint32_t smb = smem_u32(sm);

    for (int ch = 0; ch < NCH; ch++) {
        char* buf = sm + (ch & 1) * STAGE;
        char* sA = buf;
        char* sB = buf + TBYTES;

#pragma unroll
        for (int t = 0; t < 4; t++) {
            const int g = tid + t * 256;
            const int row = g >> 3, c4 = g & 7;
            const uint32_t off = (uint32_t)(row * SPAD + c4 * 4) * 2;
            *(uint2*)(sA + off) = rah[t];
            *(uint2*)(sB + off) = rbh[t];
        }
        __syncthreads();

        if (ch + 1 < NCH) load_chunk((ch + 1) * 32);  // overlap LDG with MMA

        const uint32_t bb = smb + (uint32_t)(ch & 1) * STAGE;
        const uint32_t aA = bb;
        const uint32_t aB = bb + TBYTES;

        const int arow = lane & 15;
        const int acol = (lane >> 4) << 3;
        const int brow = (lane & 7) + ((lane >> 4) << 3);
        const int bcol = ((lane >> 3) & 1) << 3;

#pragma unroll
        for (int ks = 0; ks < 2; ks++) {
            const int k0 = ks * 16;
            uint32_t ah[4][4], bh[4][2];
#pragma unroll
            for (int mt = 0; mt < 4; mt++) {
                const uint32_t o =
                    (uint32_t)((wm * 64 + mt * 16 + arow) * SPAD + k0 + acol) * 2;
                ldm_x4(ah[mt][0], ah[mt][1], ah[mt][2], ah[mt][3], aA + o);
            }
#pragma unroll
            for (int np = 0; np < 2; np++) {
                const uint32_t o =
                    (uint32_t)((wn * 32 + np * 16 + brow) * SPAD + k0 + bcol) * 2;
                ldm_x4(bh[np * 2][0], bh[np * 2][1], bh[np * 2 + 1][0], bh[np * 2 + 1][1],
                       aB + o);
            }
#pragma unroll
            for (int mt = 0; mt < 4; mt++)
#pragma unroll
                for (int nt = 0; nt < 4; nt++)
                    mma16816h(acc[mt][nt], ah[mt], bh[nt]);
        }
        __syncthreads();
    }

#pragma unroll
    for (int mt = 0; mt < 4; mt++) {
        const int r = m0 + wm * 64 + mt * 16 + (lane >> 2);
#pragma unroll
        for (int nt = 0; nt < 4; nt++) {
            const int c = n0 + wn * 32 + nt * 8 + (lane & 3) * 2;
            *(float2*)(Ceff + (size_t)r * LDC + c) =
                make_float2(acc[mt][nt][0], acc[mt][nt][1]);
            *(float2*)(Ceff + (size_t)(r + 8) * LDC + c) =
                make_float2(acc[mt][nt][2], acc[mt][nt][3]);
        }
    }
}

// ---------------------------------------------------------------------------
// RoPE + repack: g_qkvl -> fp16 Q (pre-scaled) / K / V, gate*mid -> Act tail
// ---------------------------------------------------------------------------
__global__ __launch_bounds__(256)
void repack_rope(const float* __restrict__ cosb, const float* __restrict__ sinb,
                 const float* __restrict__ gate)
{
    const int idx = blockIdx.x * 256 + threadIdx.x;
    const int row = idx / QKVLN;
    const int n   = idx - row * QKVLN;
    const int b   = row >> 11;
    const int s   = row & 2047;
    const float v = g_qkvl[idx];
    const float scale = 0.088388347648318447f;  // 1/sqrt(128)

    if (n < HID) {
        const int head = n >> 7, d = n & 127;
        const float c = cosb[s * HD + d], sn = sinb[s * HD + d];
        const float other = (d < 64) ? -g_qkvl[idx + 64] : g_qkvl[idx - 64];
        g_Qh[(((size_t)b * NH + head) * SLEN + s) * HD + d] =
            __float2half((v * c + other * sn) * scale);
    } else if (n < HID + 512) {
        const int nn = n - HID, head = nn >> 7, d = nn & 127;
        const float c = cosb[s * HD + d], sn = sinb[s * HD + d];
        const float other = (d < 64) ? -g_qkvl[idx + 64] : g_qkvl[idx - 64];
        g_Kh[(((size_t)b * NKV + head) * SLEN + s) * HD + d] =
            __float2half(v * c + other * sn);
    } else if (n < HID + 1024) {
        const int nn = n - HID - 512, head = nn >> 7, d = nn & 127;
        g_Vh[(((size_t)b * NKV + head) * SLEN + s) * HD + d] = __float2half(v);
    } else {
        g_Act[(size_t)row * ACTN + HID + (n - HID - 1024)] = gate[0] * v;
    }
}

// ---------------------------------------------------------------------------
// Flash attention on mma.sync fp16 (exact products, fp32 accum).
// CTA: 128 q-rows, 8 warps (m16 each), k-blocks of 64, causal skip.
// ---------------------------------------------------------------------------
#define LDT 136
#define ATTN_SMEM ((128 * LDT + 64 * LDT + 64 * LDT) * 2)  // 69632 B

__global__ __launch_bounds__(256, 1)
void attn_kernel()
{
    extern __shared__ __half smh[];
    __half* Qs = smh;                 // [128][LDT]
    __half* Ks = smh + 128 * LDT;     // [64][LDT]
    __half* Vs = Ks + 64 * LDT;       // [64][LDT]

    const int qt  = (int)gridDim.x - 1 - (int)blockIdx.x;  // long blocks first
    const int bh  = blockIdx.y;
    const int b   = bh >> 4;
    const int h   = bh & 15;
    const int kvh = h >> 2;
    const int tid = threadIdx.x;
    const int wid = tid >> 5;
    const int lane = tid & 31;

    const __half* Qg = g_Qh + ((size_t)(b * NH + h) * SLEN + qt * 128) * HD;
    const __half* Kg = g_Kh + (size_t)(b * NKV + kvh) * SLEN * HD;
    const __half* Vg = g_Vh + (size_t)(b * NKV + kvh) * SLEN * HD;

    // stage Q tile (128x128 fp16)
#pragma unroll
    for (int i = 0; i < 8; i++) {
        const int g = tid + i * 256;
        const int row = g >> 4, c8 = (g & 15) * 8;
        *(uint4*)(Qs + row * LDT + c8) = *(const uint4*)(Qg + row * HD + c8);
    }
    __syncthreads();

    // Q A-frags in registers (reused across all k-blocks)
    uint32_t qf[8][4];
    {
        const uint32_t qb = smem_u32(Qs) +
            (uint32_t)((wid * 16 + (lane & 15)) * LDT + ((lane >> 4) << 3)) * 2;
#pragma unroll
        for (int ks = 0; ks < 8; ks++)
            ldm_x4(qf[ks][0], qf[ks][1], qf[ks][2], qf[ks][3], qb + ks * 32);
    }

    float acc[16][4];
#pragma unroll
    for (int i = 0; i < 16; i++)
#pragma unroll
        for (int j = 0; j < 4; j++) acc[i][j] = 0.f;
    float rmax[2] = {-CUDART_INF_F, -CUDART_INF_F};
    float rsum[2] = {0.f, 0.f};

    const uint32_t kbase_a = smem_u32(Ks) +
        (uint32_t)(((lane & 7) + ((lane >> 4) << 3)) * LDT + (((lane >> 3) & 1) << 3)) * 2;
    const uint32_t vbase_a = smem_u32(Vs) +
        (uint32_t)((lane & 15) * LDT + ((lane >> 4) << 3)) * 2;

    const int nblocks = 2 * qt + 2;
    for (int kb = 0; kb < nblocks; kb++) {
        __syncthreads();
        const __half* Kt = Kg + (size_t)kb * 64 * HD;
        const __half* Vt = Vg + (size_t)kb * 64 * HD;
#pragma unroll
        for (int i = 0; i < 4; i++) {
            const int g = tid + i * 256;
            const int row = g >> 4, c8 = (g & 15) * 8;
            *(uint4*)(Ks + row * LDT + c8) = *(const uint4*)(Kt + row * HD + c8);
            *(uint4*)(Vs + row * LDT + c8) = *(const uint4*)(Vt + row * HD + c8);
        }
        __syncthreads();

        // ---- S = Q K^T ----
        float s[8][4];
#pragma unroll
        for (int i = 0; i < 8; i++)
#pragma unroll
            for (int j = 0; j < 4; j++) s[i][j] = 0.f;

#pragma unroll
        for (int ks = 0; ks < 8; ks++) {
#pragma unroll
            for (int np = 0; np < 4; np++) {
                uint32_t k0, k1, k2, k3;
                ldm_x4(k0, k1, k2, k3,
                       kbase_a + (uint32_t)(np * 16 * LDT + ks * 16) * 2);
                uint32_t bA[2] = {k0, k1}, bB[2] = {k2, k3};
                mma16816h(s[np * 2],     qf[ks], bA);
                mma16816h(s[np * 2 + 1], qf[ks], bB);
            }
        }

        // ---- causal mask on diagonal-region blocks ----
        if (kb >= 2 * qt) {
            const int kc = kb * 64 + (lane & 3) * 2;
            const int mr = qt * 128 + wid * 16 + (lane >> 2);
#pragma unroll
            for (int nt = 0; nt < 8; nt++) {
                const int c = kc + nt * 8;
                if (c > mr)         s[nt][0] = -CUDART_INF_F;
                if (c + 1 > mr)     s[nt][1] = -CUDART_INF_F;
                if (c > mr + 8)     s[nt][2] = -CUDART_INF_F;
                if (c + 1 > mr + 8) s[nt][3] = -CUDART_INF_F;
            }
        }

        // ---- online softmax (rows r and r+8; 4-lane groups share a row) ----
#pragma unroll
        for (int hf = 0; hf < 2; hf++) {
            float mx = -CUDART_INF_F;
#pragma unroll
            for (int nt = 0; nt < 8; nt++)
                mx = fmaxf(mx, fmaxf(s[nt][2 * hf], s[nt][2 * hf + 1]));
            mx = fmaxf(mx, __shfl_xor_sync(0xffffffffu, mx, 1));
            mx = fmaxf(mx, __shfl_xor_sync(0xffffffffu, mx, 2));
            const float mnew = fmaxf(rmax[hf], mx);
            const float corr = __expf(rmax[hf] - mnew);
            rmax[hf] = mnew;
            float ps = 0.f;
#pragma unroll
            for (int nt = 0; nt < 8; nt++) {
                const float p0 = __expf(s[nt][2 * hf] - mnew);
                const float p1 = __expf(s[nt][2 * hf + 1] - mnew);
                s[nt][2 * hf] = p0; s[nt][2 * hf + 1] = p1;
                ps += p0 + p1;
            }
            ps += __shfl_xor_sync(0xffffffffu, ps, 1);
            ps += __shfl_xor_sync(0xffffffffu, ps, 2);
            rsum[hf] = rsum[hf] * corr + ps;
#pragma unroll
            for (int nt = 0; nt < 16; nt++) {
                acc[nt][2 * hf]     *= corr;
                acc[nt][2 * hf + 1] *= corr;
            }
        }

        // ---- pack P into fp16 A-frags ----
        uint32_t pa[4][4];
#pragma unroll
        for (int kt = 0; kt < 4; kt++) {
            pa[kt][0] = pack_f16(s[2 * kt][0],     s[2 * kt][1]);
            pa[kt][1] = pack_f16(s[2 * kt][2],     s[2 * kt][3]);
            pa[kt][2] = pack_f16(s[2 * kt + 1][0], s[2 * kt + 1][1]);
            pa[kt][3] = pack_f16(s[2 * kt + 1][2], s[2 * kt + 1][3]);
        }

        // ---- ctx += P V  (V B-frags via ldmatrix.trans) ----
#pragma unroll
        for (int np = 0; np < 8; np++) {
#pragma unroll
            for (int kt = 0; kt < 4; kt++) {
                uint32_t v0, v1, v2, v3;
                ldm_x4t(v0, v1, v2, v3,
                        vbase_a + (uint32_t)(kt * 16 * LDT + np * 16) * 2);
                uint32_t bA[2] = {v0, v1}, bB[2] = {v2, v3};
                mma16816h(acc[np * 2],     pa[kt], bA);
                mma16816h(acc[np * 2 + 1], pa[kt], bB);
            }
        }
    }

    // ---- epilogue ----
    const float inv0 = 1.f / rsum[0];
    const float inv1 = 1.f / rsum[1];
    const int mr = qt * 128 + wid * 16 + (lane >> 2);
    float* op = g_Act + ((size_t)b * SLEN + mr) * ACTN + h * HD;
#pragma unroll
    for (int nt = 0; nt < 16; nt++) {
        const int c = nt * 8 + (lane & 3) * 2;
        *(float2*)(op + c) = make_float2(acc[nt][0] * inv0, acc[nt][1] * inv0);
        *(float2*)(op + (size_t)8 * ACTN + c) =
            make_float2(acc[nt][2] * inv1, acc[nt][3] * inv1);
    }
}

// ---------------------------------------------------------------------------
extern "C" void kernel_launch(void* const* d_in, const int* in_sizes, int n_in,
                              void* d_out, int out_size)
{
    const float* hs     = (const float*)d_in[0];
    const float* cosb   = (const float*)d_in[1];
    const float* sinb   = (const float*)d_in[2];
    // d_in[3] = attention_mask (pure causal; implemented directly)
    const float* Wq     = (const float*)d_in[4];
    const float* Wk     = (const float*)d_in[5];
    const float* Wv     = (const float*)d_in[6];
    const float* Wo     = (const float*)d_in[7];
    const float* Wl_in  = (const float*)d_in[8];
    const float* Wl_out = (const float*)d_in[9];
    const float* gate   = (const float*)d_in[10];
    float* out = (float*)d_out;

    cudaFuncSetAttribute(attn_kernel,
                         cudaFuncAttributeMaxDynamicSharedMemorySize, ATTN_SMEM);
    cudaFuncSetAttribute(tc_gemm<0>,
                         cudaFuncAttributeMaxDynamicSharedMemorySize, GEMM_SMEM);
    cudaFuncSetAttribute(tc_gemm<1>,
                         cudaFuncAttributeMaxDynamicSharedMemorySize, GEMM_SMEM);

    // 1) fused [Q|K|V|latent_mid] projection (mma.sync fp16 single-pass)
    tc_gemm<0><<<dim3(QKVLN / 128, ROWS / 128), 256, GEMM_SMEM>>>(
        hs, Wq, Wk, Wv, Wl_in, nullptr);
    // 2) RoPE + repack -> fp16 Q/K/V (+ gate*mid into Act tail)
    repack_rope<<<(ROWS * QKVLN) / 256, 256>>>(cosb, sinb, gate);
    // 3) flash attention (fp16 mma) -> Act[:, 0:2048]
    attn_kernel<<<dim3(SLEN / 128, BATCH * NH), 256, ATTN_SMEM>>>();
    // 4) out = Act @ [Wo | Wl_out]^T (mma.sync fp16 single-pass)
    tc_gemm<1><<<dim3(HID / 128, ROWS / 128), 256, GEMM_SMEM>>>(
        nullptr, Wo, Wl_out, nullptr, nullptr, out);
}

// round 7
// speedup vs baseline: 6.0969x; 1.1760x over previous
#include <cuda_runtime.h>
#include <cuda_fp16.h>
#include <math_constants.h>
#include <cstdint>

#define BATCH 2
#define SLEN  2048
#define HID   2048
#define NH    16
#define NKV   4
#define HD    128
#define LAT   256
#define ROWS  (BATCH * SLEN)          // 4096
#define QKVLN (HID + 512 + 512 + LAT) // 3328
#define ACTN  (HID + LAT)             // 2304

// Scratch (static device globals: allocation-free per harness rules).
// NOTE: referenced ONLY inside kernel bodies — host code cannot take the
// address of a __device__ variable (R6's failure mode).
__device__ float  g_qkvl[(size_t)ROWS * QKVLN];             // fp32 QKV+latent mid
__device__ __half g_hsh[(size_t)ROWS * HID];                // fp16 hidden states
__device__ __half g_W1h[(size_t)QKVLN * HID];               // fp16 [Wq|Wk|Wv|Wl_in]
__device__ __half g_W2h[(size_t)HID * ACTN];                // fp16 [Wo|Wl_out] rows
__device__ __half g_Qh[(size_t)BATCH * NH * SLEN * HD];     // fp16, pre-scaled
__device__ __half g_Kh[(size_t)BATCH * NKV * SLEN * HD];
__device__ __half g_Vh[(size_t)BATCH * NKV * SLEN * HD];
__device__ __half g_Acth[(size_t)ROWS * ACTN];              // fp16 [ctx | gate*mid]

// ---------------------------------------------------------------------------
// helpers (base sm_103-legal: mma.sync + ldmatrix + cp.async, no tcgen05)
// ---------------------------------------------------------------------------
__device__ __forceinline__ uint32_t smem_u32(const void* p) {
    uint32_t a;
    asm("{ .reg .u64 t; cvta.to.shared.u64 t, %1; cvt.u32.u64 %0, t; }"
        : "=r"(a) : "l"(p));
    return a;
}
__device__ __forceinline__ void ldm_x4(uint32_t& r0, uint32_t& r1,
                                       uint32_t& r2, uint32_t& r3, uint32_t addr) {
    asm volatile("ldmatrix.sync.aligned.m8n8.x4.shared.b16 {%0,%1,%2,%3}, [%4];"
                 : "=r"(r0), "=r"(r1), "=r"(r2), "=r"(r3) : "r"(addr));
}
__device__ __forceinline__ void ldm_x4t(uint32_t& r0, uint32_t& r1,
                                        uint32_t& r2, uint32_t& r3, uint32_t addr) {
    asm volatile("ldmatrix.sync.aligned.m8n8.x4.trans.shared.b16 {%0,%1,%2,%3}, [%4];"
                 : "=r"(r0), "=r"(r1), "=r"(r2), "=r"(r3) : "r"(addr));
}
__device__ __forceinline__ void mma16816h(float* c, const uint32_t* a, const uint32_t* b) {
    asm volatile(
        "mma.sync.aligned.m16n8k16.row.col.f32.f16.f16.f32 "
        "{%0,%1,%2,%3}, {%4,%5,%6,%7}, {%8,%9}, {%0,%1,%2,%3};"
        : "+f"(c[0]), "+f"(c[1]), "+f"(c[2]), "+f"(c[3])
        : "r"(a[0]), "r"(a[1]), "r"(a[2]), "r"(a[3]), "r"(b[0]), "r"(b[1]));
}
__device__ __forceinline__ uint32_t pack_f16(float lo, float hi) {
    uint32_t r;
    asm("cvt.rn.f16x2.f32 %0, %1, %2;" : "=r"(r) : "f"(hi), "f"(lo));
    return r;
}
__device__ __forceinline__ void cp16(uint32_t dst, const void* src) {
    asm volatile("cp.async.cg.shared.global [%0], [%1], 16;"
                 :: "r"(dst), "l"(src) : "memory");
}
#define CP_COMMIT() asm volatile("cp.async.commit_group;" ::: "memory")
#define CP_WAIT(N)  asm volatile("cp.async.wait_group %0;" :: "n"(N) : "memory")

// ---------------------------------------------------------------------------
// One-time fp32 -> fp16 conversion of hs + packed weights
// ---------------------------------------------------------------------------
#define HS4 (ROWS * HID / 4)        // 2097152
#define W14 (QKVLN * HID / 4)       // 1703936
#define W24 (HID * ACTN / 4)        // 1179648
#define CONV_BLOCKS ((HS4 + W14 + W24) / 256)

__global__ __launch_bounds__(256)
void convert_inputs(const float* __restrict__ hs,
                    const float* __restrict__ Wq, const float* __restrict__ Wk,
                    const float* __restrict__ Wv, const float* __restrict__ Wo,
                    const float* __restrict__ Wl_in, const float* __restrict__ Wl_out)
{
    int idx = blockIdx.x * 256 + threadIdx.x;
    float4 v;
    __half* dst;
    if (idx < HS4) {
        v = ((const float4*)hs)[idx];
        dst = g_hsh + (size_t)idx * 4;
    } else if ((idx -= HS4) < W14) {
        const int n = idx >> 9;               // HID/4 = 512 float4 per row
        const int c = (idx & 511) * 4;
        const float* w;
        if (n < HID)             w = Wq + (size_t)n * HID;
        else if (n < HID + 512)  w = Wk + (size_t)(n - HID) * HID;
        else if (n < HID + 1024) w = Wv + (size_t)(n - HID - 512) * HID;
        else                     w = Wl_in + (size_t)(n - HID - 1024) * HID;
        v = *(const float4*)(w + c);
        dst = g_W1h + (size_t)n * HID + c;
    } else {
        idx -= W14;
        const int n = idx / (ACTN / 4);       // 576 float4 per row
        const int c = (idx - n * (ACTN / 4)) * 4;
        if (c < HID) v = *(const float4*)(Wo + (size_t)n * HID + c);
        else         v = *(const float4*)(Wl_out + (size_t)n * LAT + (c - HID));
        dst = g_W2h + (size_t)n * ACTN + c;
    }
    *(uint2*)dst = make_uint2(pack_f16(v.x, v.y), pack_f16(v.z, v.w));
}

// ---------------------------------------------------------------------------
// fp16 NT GEMM, cp.async 3-stage pipeline: C[M,N] = A[M,K] * B[N,K]^T
// 128x128 CTA tile, BK=32, 8 warps (2x4), warp tile 64x32. 2 CTAs/SM.
// MODE 0: A=g_hsh, B=g_W1h, C=g_qkvl (internal).  MODE 1: A=g_Acth, B=g_W2h, C=out.
// ---------------------------------------------------------------------------
#define SPAD      40                        // halfs per row (32 + 8 pad); 80 B
#define TBYTES    (128 * SPAD * 2)          // 10240 B
#define STAGE_B   (2 * TBYTES)              // 20480 B (A + B)
#define NSTAGES   3
#define GEMM_SMEM (NSTAGES * STAGE_B)       // 61440 B

template <int MODE>
__global__ __launch_bounds__(256, 2)
void tc_gemm(float* __restrict__ Cout)
{
    constexpr int LDK = (MODE == 0) ? HID : ACTN;   // K stride for A and B
    constexpr int LDC = (MODE == 0) ? QKVLN : HID;
    constexpr int NCH = LDK / 32;

    const __half* __restrict__ A = (MODE == 0) ? g_hsh : g_Acth;
    const __half* __restrict__ B = (MODE == 0) ? g_W1h : g_W2h;
    float* __restrict__ C        = (MODE == 0) ? g_qkvl : Cout;

    extern __shared__ __align__(16) char sm[];
    const uint32_t smb = smem_u32(sm);

    const int n0  = blockIdx.x * 128;
    const int m0  = blockIdx.y * 128;
    const int tid = threadIdx.x;
    const int wid = tid >> 5;
    const int lane = tid & 31;
    const int wm = wid >> 2;
    const int wn = wid & 3;

    // cp.async per-thread slots: 2 x (A row, B row) of 8 halfs each
    const int crow = tid >> 2;
    const int ccol = (tid & 3) * 8;

    auto cp_stage = [&](int ch) {
        if (ch < NCH) {
            const int k0 = ch * 32;
            const uint32_t sb = smb + (uint32_t)(ch % NSTAGES) * STAGE_B;
#pragma unroll
            for (int t = 0; t < 2; t++) {
                const int row = crow + t * 64;
                const uint32_t so = (uint32_t)(row * SPAD + ccol) * 2;
                cp16(sb + so, A + (size_t)(m0 + row) * LDK + k0 + ccol);
                cp16(sb + TBYTES + so, B + (size_t)(n0 + row) * LDK + k0 + ccol);
            }
        }
        CP_COMMIT();
    };

    float acc[4][4][4];
#pragma unroll
    for (int i = 0; i < 4; i++)
#pragma unroll
        for (int j = 0; j < 4; j++)
#pragma unroll
            for (int k = 0; k < 4; k++) acc[i][j][k] = 0.f;

    cp_stage(0);
    cp_stage(1);

    const int arow = lane & 15;
    const int acol = (lane >> 4) << 3;
    const int brow = (lane & 7) + ((lane >> 4) << 3);
    const int bcol = ((lane >> 3) & 1) << 3;

    for (int ch = 0; ch < NCH; ch++) {
        CP_WAIT(1);                 // stage ch resident (own copies)
        __syncthreads();            // visible to all; MMA(ch-1) finished
        cp_stage(ch + 2);           // prefetch into buffer (ch-1)%3

        const uint32_t bb = smb + (uint32_t)(ch % NSTAGES) * STAGE_B;
        const uint32_t aA = bb;
        const uint32_t aB = bb + TBYTES;

#pragma unroll
        for (int ks = 0; ks < 2; ks++) {
            const int k0 = ks * 16;
            uint32_t ah[4][4], bh[4][2];
#pragma unroll
            for (int mt = 0; mt < 4; mt++) {
                const uint32_t o =
                    (uint32_t)((wm * 64 + mt * 16 + arow) * SPAD + k0 + acol) * 2;
                ldm_x4(ah[mt][0], ah[mt][1], ah[mt][2], ah[mt][3], aA + o);
            }
#pragma unroll
            for (int np = 0; np < 2; np++) {
                const uint32_t o =
                    (uint32_t)((wn * 32 + np * 16 + brow) * SPAD + k0 + bcol) * 2;
                ldm_x4(bh[np * 2][0], bh[np * 2][1], bh[np * 2 + 1][0], bh[np * 2 + 1][1],
                       aB + o);
            }
#pragma unroll
            for (int mt = 0; mt < 4; mt++)
#pragma unroll
                for (int nt = 0; nt < 4; nt++)
                    mma16816h(acc[mt][nt], ah[mt], bh[nt]);
        }
        __syncthreads();            // MMA(ch) done before buffer overwrite
    }

#pragma unroll
    for (int mt = 0; mt < 4; mt++) {
        const int r = m0 + wm * 64 + mt * 16 + (lane >> 2);
#pragma unroll
        for (int nt = 0; nt < 4; nt++) {
            const int c = n0 + wn * 32 + nt * 8 + (lane & 3) * 2;
            *(float2*)(C + (size_t)r * LDC + c) =
                make_float2(acc[mt][nt][0], acc[mt][nt][1]);
            *(float2*)(C + (size_t)(r + 8) * LDC + c) =
                make_float2(acc[mt][nt][2], acc[mt][nt][3]);
        }
    }
}

// ---------------------------------------------------------------------------
// RoPE + repack: g_qkvl -> fp16 Q (pre-scaled) / K / V, gate*mid -> Acth tail
// ---------------------------------------------------------------------------
__global__ __launch_bounds__(256)
void repack_rope(const float* __restrict__ cosb, const float* __restrict__ sinb,
                 const float* __restrict__ gate)
{
    const int idx = blockIdx.x * 256 + threadIdx.x;
    const int row = idx / QKVLN;
    const int n   = idx - row * QKVLN;
    const int b   = row >> 11;
    const int s   = row & 2047;
    const float v = g_qkvl[idx];
    const float scale = 0.088388347648318447f;  // 1/sqrt(128)

    if (n < HID) {
        const int head = n >> 7, d = n & 127;
        const float c = cosb[s * HD + d], sn = sinb[s * HD + d];
        const float other = (d < 64) ? -g_qkvl[idx + 64] : g_qkvl[idx - 64];
        g_Qh[(((size_t)b * NH + head) * SLEN + s) * HD + d] =
            __float2half((v * c + other * sn) * scale);
    } else if (n < HID + 512) {
        const int nn = n - HID, head = nn >> 7, d = nn & 127;
        const float c = cosb[s * HD + d], sn = sinb[s * HD + d];
        const float other = (d < 64) ? -g_qkvl[idx + 64] : g_qkvl[idx - 64];
        g_Kh[(((size_t)b * NKV + head) * SLEN + s) * HD + d] =
            __float2half(v * c + other * sn);
    } else if (n < HID + 1024) {
        const int nn = n - HID - 512, head = nn >> 7, d = nn & 127;
        g_Vh[(((size_t)b * NKV + head) * SLEN + s) * HD + d] = __float2half(v);
    } else {
        g_Acth[(size_t)row * ACTN + HID + (n - HID - 1024)] =
            __float2half(gate[0] * v);
    }
}

// ---------------------------------------------------------------------------
// Flash attention on mma.sync fp16 (exact products, fp32 accum).
// CTA: 128 q-rows, 8 warps (m16 each), k-blocks of 64, causal skip.
// ---------------------------------------------------------------------------
#define LDT 136
#define ATTN_SMEM ((128 * LDT + 64 * LDT + 64 * LDT) * 2)  // 69632 B

__global__ __launch_bounds__(256, 1)
void attn_kernel()
{
    extern __shared__ __half smh[];
    __half* Qs = smh;                 // [128][LDT]
    __half* Ks = smh + 128 * LDT;     // [64][LDT]
    __half* Vs = Ks + 64 * LDT;       // [64][LDT]

    const int qt  = (int)gridDim.x - 1 - (int)blockIdx.x;  // long blocks first
    const int bh  = blockIdx.y;
    const int b   = bh >> 4;
    const int h   = bh & 15;
    const int kvh = h >> 2;
    const int tid = threadIdx.x;
    const int wid = tid >> 5;
    const int lane = tid & 31;

    const __half* Qg = g_Qh + ((size_t)(b * NH + h) * SLEN + qt * 128) * HD;
    const __half* Kg = g_Kh + (size_t)(b * NKV + kvh) * SLEN * HD;
    const __half* Vg = g_Vh + (size_t)(b * NKV + kvh) * SLEN * HD;

    // stage Q tile (128x128 fp16)
#pragma unroll
    for (int i = 0; i < 8; i++) {
        const int g = tid + i * 256;
        const int row = g >> 4, c8 = (g & 15) * 8;
        *(uint4*)(Qs + row * LDT + c8) = *(const uint4*)(Qg + row * HD + c8);
    }
    __syncthreads();

    // Q A-frags in registers (reused across all k-blocks)
    uint32_t qf[8][4];
    {
        const uint32_t qb = smem_u32(Qs) +
            (uint32_t)((wid * 16 + (lane & 15)) * LDT + ((lane >> 4) << 3)) * 2;
#pragma unroll
        for (int ks = 0; ks < 8; ks++)
            ldm_x4(qf[ks][0], qf[ks][1], qf[ks][2], qf[ks][3], qb + ks * 32);
    }

    float acc[16][4];
#pragma unroll
    for (int i = 0; i < 16; i++)
#pragma unroll
        for (int j = 0; j < 4; j++) acc[i][j] = 0.f;
    float rmax[2] = {-CUDART_INF_F, -CUDART_INF_F};
    float rsum[2] = {0.f, 0.f};

    const uint32_t kbase_a = smem_u32(Ks) +
        (uint32_t)(((lane & 7) + ((lane >> 4) << 3)) * LDT + (((lane >> 3) & 1) << 3)) * 2;
    const uint32_t vbase_a = smem_u32(Vs) +
        (uint32_t)((lane & 15) * LDT + ((lane >> 4) << 3)) * 2;

    const int nblocks = 2 * qt + 2;
    for (int kb = 0; kb < nblocks; kb++) {
        __syncthreads();
        const __half* Kt = Kg + (size_t)kb * 64 * HD;
        const __half* Vt = Vg + (size_t)kb * 64 * HD;
#pragma unroll
        for (int i = 0; i < 4; i++) {
            const int g = tid + i * 256;
            const int row = g >> 4, c8 = (g & 15) * 8;
            *(uint4*)(Ks + row * LDT + c8) = *(const uint4*)(Kt + row * HD + c8);
            *(uint4*)(Vs + row * LDT + c8) = *(const uint4*)(Vt + row * HD + c8);
        }
        __syncthreads();

        // ---- S = Q K^T ----
        float s[8][4];
#pragma unroll
        for (int i = 0; i < 8; i++)
#pragma unroll
            for (int j = 0; j < 4; j++) s[i][j] = 0.f;

#pragma unroll
        for (int ks = 0; ks < 8; ks++) {
#pragma unroll
            for (int np = 0; np < 4; np++) {
                uint32_t k0, k1, k2, k3;
                ldm_x4(k0, k1, k2, k3,
                       kbase_a + (uint32_t)(np * 16 * LDT + ks * 16) * 2);
                uint32_t bA[2] = {k0, k1}, bB[2] = {k2, k3};
                mma16816h(s[np * 2],     qf[ks], bA);
                mma16816h(s[np * 2 + 1], qf[ks], bB);
            }
        }

        // ---- causal mask on diagonal-region blocks ----
        if (kb >= 2 * qt) {
            const int kc = kb * 64 + (lane & 3) * 2;
            const int mr = qt * 128 + wid * 16 + (lane >> 2);
#pragma unroll
            for (int nt = 0; nt < 8; nt++) {
                const int c = kc + nt * 8;
                if (c > mr)         s[nt][0] = -CUDART_INF_F;
                if (c + 1 > mr)     s[nt][1] = -CUDART_INF_F;
                if (c > mr + 8)     s[nt][2] = -CUDART_INF_F;
                if (c + 1 > mr + 8) s[nt][3] = -CUDART_INF_F;
            }
        }

        // ---- online softmax (rows r and r+8; 4-lane groups share a row) ----
#pragma unroll
        for (int hf = 0; hf < 2; hf++) {
            float mx = -CUDART_INF_F;
#pragma unroll
            for (int nt = 0; nt < 8; nt++)
                mx = fmaxf(mx, fmaxf(s[nt][2 * hf], s[nt][2 * hf + 1]));
            mx = fmaxf(mx, __shfl_xor_sync(0xffffffffu, mx, 1));
            mx = fmaxf(mx, __shfl_xor_sync(0xffffffffu, mx, 2));
            const float mnew = fmaxf(rmax[hf], mx);
            const float corr = __expf(rmax[hf] - mnew);
            rmax[hf] = mnew;
            float ps = 0.f;
#pragma unroll
            for (int nt = 0; nt < 8; nt++) {
                const float p0 = __expf(s[nt][2 * hf] - mnew);
                const float p1 = __expf(s[nt][2 * hf + 1] - mnew);
                s[nt][2 * hf] = p0; s[nt][2 * hf + 1] = p1;
                ps += p0 + p1;
            }
            ps += __shfl_xor_sync(0xffffffffu, ps, 1);
            ps += __shfl_xor_sync(0xffffffffu, ps, 2);
            rsum[hf] = rsum[hf] * corr + ps;
#pragma unroll
            for (int nt = 0; nt < 16; nt++) {
                acc[nt][2 * hf]     *= corr;
                acc[nt][2 * hf + 1] *= corr;
            }
        }

        // ---- pack P into fp16 A-frags ----
        uint32_t pa[4][4];
#pragma unroll
        for (int kt = 0; kt < 4; kt++) {
            pa[kt][0] = pack_f16(s[2 * kt][0],     s[2 * kt][1]);
            pa[kt][1] = pack_f16(s[2 * kt][2],     s[2 * kt][3]);
            pa[kt][2] = pack_f16(s[2 * kt + 1][0], s[2 * kt + 1][1]);
            pa[kt][3] = pack_f16(s[2 * kt + 1][2], s[2 * kt + 1][3]);
        }

        // ---- ctx += P V  (V B-frags via ldmatrix.trans) ----
#pragma unroll
        for (int np = 0; np < 8; np++) {
#pragma unroll
            for (int kt = 0; kt < 4; kt++) {
                uint32_t v0, v1, v2, v3;
                ldm_x4t(v0, v1, v2, v3,
                        vbase_a + (uint32_t)(kt * 16 * LDT + np * 16) * 2);
                uint32_t bA[2] = {v0, v1}, bB[2] = {v2, v3};
                mma16816h(acc[np * 2],     pa[kt], bA);
                mma16816h(acc[np * 2 + 1], pa[kt], bB);
            }
        }
    }

    // ---- epilogue: fp16 ctx into g_Acth ----
    const float inv0 = 1.f / rsum[0];
    const float inv1 = 1.f / rsum[1];
    const int mr = qt * 128 + wid * 16 + (lane >> 2);
    __half* op = g_Acth + ((size_t)b * SLEN + mr) * ACTN + h * HD;
#pragma unroll
    for (int nt = 0; nt < 16; nt++) {
        const int c = nt * 8 + (lane & 3) * 2;
        *(uint32_t*)(op + c) = pack_f16(acc[nt][0] * inv0, acc[nt][1] * inv0);
        *(uint32_t*)(op + (size_t)8 * ACTN + c) =
            pack_f16(acc[nt][2] * inv1, acc[nt][3] * inv1);
    }
}

// ---------------------------------------------------------------------------
extern "C" void kernel_launch(void* const* d_in, const int* in_sizes, int n_in,
                              void* d_out, int out_size)
{
    const float* hs     = (const float*)d_in[0];
    const float* cosb   = (const float*)d_in[1];
    const float* sinb   = (const float*)d_in[2];
    // d_in[3] = attention_mask (pure causal; implemented directly)
    const float* Wq     = (const float*)d_in[4];
    const float* Wk     = (const float*)d_in[5];
    const float* Wv     = (const float*)d_in[6];
    const float* Wo     = (const float*)d_in[7];
    const float* Wl_in  = (const float*)d_in[8];
    const float* Wl_out = (const float*)d_in[9];
    const float* gate   = (const float*)d_in[10];
    float* out = (float*)d_out;

    cudaFuncSetAttribute(attn_kernel,
                         cudaFuncAttributeMaxDynamicSharedMemorySize, ATTN_SMEM);
    cudaFuncSetAttribute(tc_gemm<0>,
                         cudaFuncAttributeMaxDynamicSharedMemorySize, GEMM_SMEM);
    cudaFuncSetAttribute(tc_gemm<1>,
                         cudaFuncAttributeMaxDynamicSharedMemorySize, GEMM_SMEM);

    // 0) fp32 -> fp16 conversion of hs + packed weights
    convert_inputs<<<CONV_BLOCKS, 256>>>(hs, Wq, Wk, Wv, Wo, Wl_in, Wl_out);
    // 1) fused [Q|K|V|latent_mid] projection (fp16 cp.async pipeline)
    tc_gemm<0><<<dim3(QKVLN / 128, ROWS / 128), 256, GEMM_SMEM>>>(nullptr);
    // 2) RoPE + repack -> fp16 Q/K/V (+ gate*mid into Acth tail)
    repack_rope<<<(ROWS * QKVLN) / 256, 256>>>(cosb, sinb, gate);
    // 3) flash attention (fp16 mma) -> Acth[:, 0:2048]
    attn_kernel<<<dim3(SLEN / 128, BATCH * NH), 256, ATTN_SMEM>>>();
    // 4) out = Acth @ [Wo | Wl_out]^T (fp16 cp.async pipeline)
    tc_gemm<1><<<dim3(HID / 128, ROWS / 128), 256, GEMM_SMEM>>>(out);
}

// round 8
// speedup vs baseline: 6.2330x; 1.0223x over previous
#include <cuda_runtime.h>
#include <cuda_fp16.h>
#include <math_constants.h>
#include <cstdint>

#define BATCH 2
#define SLEN  2048
#define HID   2048
#define NH    16
#define NKV   4
#define HD    128
#define LAT   256
#define ROWS  (BATCH * SLEN)          // 4096
#define QKVLN (HID + 512 + 512 + LAT) // 3328
#define ACTN  (HID + LAT)             // 2304

// Scratch (static device globals; referenced only inside kernel bodies)
__device__ float  g_qkvl[(size_t)ROWS * QKVLN];             // fp32 QKV+latent mid
__device__ __half g_hsh[(size_t)ROWS * HID];                // fp16 hidden states
__device__ __half g_W1h[(size_t)QKVLN * HID];               // fp16 [Wq|Wk|Wv|Wl_in]
__device__ __half g_W2h[(size_t)HID * ACTN];                // fp16 [Wo|Wl_out] rows
__device__ __half g_Qh[(size_t)BATCH * NH * SLEN * HD];     // fp16, pre-scaled
__device__ __half g_Kh[(size_t)BATCH * NKV * SLEN * HD];
__device__ __half g_Vh[(size_t)BATCH * NKV * SLEN * HD];
__device__ __half g_Acth[(size_t)ROWS * ACTN];              // fp16 [ctx | gate*mid]

// ---------------------------------------------------------------------------
// helpers (base sm_103-legal: mma.sync + ldmatrix + cp.async, no tcgen05)
// ---------------------------------------------------------------------------
__device__ __forceinline__ uint32_t smem_u32(const void* p) {
    uint32_t a;
    asm("{ .reg .u64 t; cvta.to.shared.u64 t, %1; cvt.u32.u64 %0, t; }"
        : "=r"(a) : "l"(p));
    return a;
}
__device__ __forceinline__ void ldm_x4(uint32_t& r0, uint32_t& r1,
                                       uint32_t& r2, uint32_t& r3, uint32_t addr) {
    asm volatile("ldmatrix.sync.aligned.m8n8.x4.shared.b16 {%0,%1,%2,%3}, [%4];"
                 : "=r"(r0), "=r"(r1), "=r"(r2), "=r"(r3) : "r"(addr));
}
__device__ __forceinline__ void ldm_x4t(uint32_t& r0, uint32_t& r1,
                                        uint32_t& r2, uint32_t& r3, uint32_t addr) {
    asm volatile("ldmatrix.sync.aligned.m8n8.x4.trans.shared.b16 {%0,%1,%2,%3}, [%4];"
                 : "=r"(r0), "=r"(r1), "=r"(r2), "=r"(r3) : "r"(addr));
}
__device__ __forceinline__ void mma16816h(float* c, const uint32_t* a, const uint32_t* b) {
    asm volatile(
        "mma.sync.aligned.m16n8k16.row.col.f32.f16.f16.f32 "
        "{%0,%1,%2,%3}, {%4,%5,%6,%7}, {%8,%9}, {%0,%1,%2,%3};"
        : "+f"(c[0]), "+f"(c[1]), "+f"(c[2]), "+f"(c[3])
        : "r"(a[0]), "r"(a[1]), "r"(a[2]), "r"(a[3]), "r"(b[0]), "r"(b[1]));
}
__device__ __forceinline__ uint32_t pack_f16(float lo, float hi) {
    uint32_t r;
    asm("cvt.rn.f16x2.f32 %0, %1, %2;" : "=r"(r) : "f"(hi), "f"(lo));
    return r;
}
__device__ __forceinline__ void cp16(uint32_t dst, const void* src) {
    asm volatile("cp.async.cg.shared.global [%0], [%1], 16;"
                 :: "r"(dst), "l"(src) : "memory");
}
#define CP_COMMIT() asm volatile("cp.async.commit_group;" ::: "memory")
#define CP_WAIT(N)  asm volatile("cp.async.wait_group %0;" :: "n"(N) : "memory")

// ---------------------------------------------------------------------------
// One-time fp32 -> fp16 conversion of hs + packed weights
// ---------------------------------------------------------------------------
#define HS4 (ROWS * HID / 4)        // 2097152
#define W14 (QKVLN * HID / 4)       // 1703936
#define W24 (HID * ACTN / 4)        // 1179648
#define CONV_BLOCKS ((HS4 + W14 + W24) / 256)

__global__ __launch_bounds__(256)
void convert_inputs(const float* __restrict__ hs,
                    const float* __restrict__ Wq, const float* __restrict__ Wk,
                    const float* __restrict__ Wv, const float* __restrict__ Wo,
                    const float* __restrict__ Wl_in, const float* __restrict__ Wl_out)
{
    int idx = blockIdx.x * 256 + threadIdx.x;
    float4 v;
    __half* dst;
    if (idx < HS4) {
        v = ((const float4*)hs)[idx];
        dst = g_hsh + (size_t)idx * 4;
    } else if ((idx -= HS4) < W14) {
        const int n = idx >> 9;               // HID/4 = 512 float4 per row
        const int c = (idx & 511) * 4;
        const float* w;
        if (n < HID)             w = Wq + (size_t)n * HID;
        else if (n < HID + 512)  w = Wk + (size_t)(n - HID) * HID;
        else if (n < HID + 1024) w = Wv + (size_t)(n - HID - 512) * HID;
        else                     w = Wl_in + (size_t)(n - HID - 1024) * HID;
        v = *(const float4*)(w + c);
        dst = g_W1h + (size_t)n * HID + c;
    } else {
        idx -= W14;
        const int n = idx / (ACTN / 4);       // 576 float4 per row
        const int c = (idx - n * (ACTN / 4)) * 4;
        if (c < HID) v = *(const float4*)(Wo + (size_t)n * HID + c);
        else         v = *(const float4*)(Wl_out + (size_t)n * LAT + (c - HID));
        dst = g_W2h + (size_t)n * ACTN + c;
    }
    *(uint2*)dst = make_uint2(pack_f16(v.x, v.y), pack_f16(v.z, v.w));
}

// ---------------------------------------------------------------------------
// fp16 NT GEMM, cp.async 3-stage: C[M,N] = A[M,K] * B[N,K]^T
// 128x128 CTA tile, BK=32, 4 warps (2x2), warp tile 64x64. 2 CTAs/SM.
// ---------------------------------------------------------------------------
#define SPAD      40                        // halfs per row (32 + 8 pad); 80 B
#define TBYTES    (128 * SPAD * 2)          // 10240 B
#define STAGE_B   (2 * TBYTES)              // 20480 B (A + B)
#define NSTAGES   3
#define GEMM_SMEM (NSTAGES * STAGE_B)       // 61440 B

template <int MODE>
__global__ __launch_bounds__(128, 2)
void tc_gemm(float* __restrict__ Cout)
{
    constexpr int LDK = (MODE == 0) ? HID : ACTN;
    constexpr int LDC = (MODE == 0) ? QKVLN : HID;
    constexpr int NCH = LDK / 32;

    const __half* __restrict__ A = (MODE == 0) ? g_hsh : g_Acth;
    const __half* __restrict__ B = (MODE == 0) ? g_W1h : g_W2h;
    float* __restrict__ C        = (MODE == 0) ? g_qkvl : Cout;

    extern __shared__ __align__(16) char sm[];
    const uint32_t smb = smem_u32(sm);

    const int n0  = blockIdx.x * 128;
    const int m0  = blockIdx.y * 128;
    const int tid = threadIdx.x;
    const int wid = tid >> 5;
    const int lane = tid & 31;
    const int wm = wid >> 1;       // 0..1 -> m offset wm*64
    const int wn = wid & 1;        // 0..1 -> n offset wn*64

    auto cp_stage = [&](int ch) {
        if (ch < NCH) {
            const int k0 = ch * 32;
            const uint32_t sb = smb + (uint32_t)(ch % NSTAGES) * STAGE_B;
#pragma unroll
            for (int t = 0; t < 2; t++) {
                const int row = (tid >> 1) + t * 64;
#pragma unroll
                for (int cc = 0; cc < 2; cc++) {
                    const int col = (tid & 1) * 16 + cc * 8;
                    const uint32_t so = (uint32_t)(row * SPAD + col) * 2;
                    cp16(sb + so, A + (size_t)(m0 + row) * LDK + k0 + col);
                    cp16(sb + TBYTES + so, B + (size_t)(n0 + row) * LDK + k0 + col);
                }
            }
        }
        CP_COMMIT();
    };

    float acc[4][8][4];
#pragma unroll
    for (int i = 0; i < 4; i++)
#pragma unroll
        for (int j = 0; j < 8; j++)
#pragma unroll
            for (int k = 0; k < 4; k++) acc[i][j][k] = 0.f;

    cp_stage(0);
    cp_stage(1);

    const int arow = lane & 15;
    const int acol = (lane >> 4) << 3;
    const int brow = (lane & 7) + ((lane >> 4) << 3);
    const int bcol = ((lane >> 3) & 1) << 3;

    for (int ch = 0; ch < NCH; ch++) {
        CP_WAIT(1);
        __syncthreads();
        cp_stage(ch + 2);

        const uint32_t bb = smb + (uint32_t)(ch % NSTAGES) * STAGE_B;
        const uint32_t aA = bb;
        const uint32_t aB = bb + TBYTES;

#pragma unroll
        for (int ks = 0; ks < 2; ks++) {
            const int k0 = ks * 16;
            uint32_t ah[4][4], bh[8][2];
#pragma unroll
            for (int mt = 0; mt < 4; mt++) {
                const uint32_t o =
                    (uint32_t)((wm * 64 + mt * 16 + arow) * SPAD + k0 + acol) * 2;
                ldm_x4(ah[mt][0], ah[mt][1], ah[mt][2], ah[mt][3], aA + o);
            }
#pragma unroll
            for (int np = 0; np < 4; np++) {
                const uint32_t o =
                    (uint32_t)((wn * 64 + np * 16 + brow) * SPAD + k0 + bcol) * 2;
                ldm_x4(bh[np * 2][0], bh[np * 2][1], bh[np * 2 + 1][0], bh[np * 2 + 1][1],
                       aB + o);
            }
#pragma unroll
            for (int mt = 0; mt < 4; mt++)
#pragma unroll
                for (int nt = 0; nt < 8; nt++)
                    mma16816h(acc[mt][nt], ah[mt], bh[nt]);
        }
        __syncthreads();
    }

#pragma unroll
    for (int mt = 0; mt < 4; mt++) {
        const int r = m0 + wm * 64 + mt * 16 + (lane >> 2);
#pragma unroll
        for (int nt = 0; nt < 8; nt++) {
            const int c = n0 + wn * 64 + nt * 8 + (lane & 3) * 2;
            *(float2*)(C + (size_t)r * LDC + c) =
                make_float2(acc[mt][nt][0], acc[mt][nt][1]);
            *(float2*)(C + (size_t)(r + 8) * LDC + c) =
                make_float2(acc[mt][nt][2], acc[mt][nt][3]);
        }
    }
}

// ---------------------------------------------------------------------------
// RoPE + repack (float4-vectorized): g_qkvl -> fp16 Q (pre-scaled)/K/V, Acth tail
// ---------------------------------------------------------------------------
__global__ __launch_bounds__(256)
void repack_rope(const float* __restrict__ cosb, const float* __restrict__ sinb,
                 const float* __restrict__ gate)
{
    const int idx4 = blockIdx.x * 256 + threadIdx.x;   // ROWS*QKVLN/4 total
    const int row  = idx4 / (QKVLN / 4);
    const int n    = (idx4 - row * (QKVLN / 4)) * 4;
    const int b    = row >> 11;
    const int s    = row & 2047;
    const size_t base = (size_t)row * QKVLN + n;
    const float4 v = *(const float4*)(g_qkvl + base);
    const float scale = 0.088388347648318447f;  // 1/sqrt(128)

    if (n < HID + 512) {                 // Q or K + RoPE
        const int nn  = (n < HID) ? n : n - HID;
        const int head = nn >> 7, d = nn & 127;
        const float4 c  = *(const float4*)(cosb + s * HD + d);
        const float4 sn = *(const float4*)(sinb + s * HD + d);
        const float4 o = (d < 64) ? *(const float4*)(g_qkvl + base + 64)
                                  : *(const float4*)(g_qkvl + base - 64);
        const float sgn = (d < 64) ? -1.f : 1.f;
        float rx = v.x * c.x + sgn * o.x * sn.x;
        float ry = v.y * c.y + sgn * o.y * sn.y;
        float rz = v.z * c.z + sgn * o.z * sn.z;
        float rw = v.w * c.w + sgn * o.w * sn.w;
        if (n < HID) {
            rx *= scale; ry *= scale; rz *= scale; rw *= scale;
            __half* dst = g_Qh + (((size_t)b * NH + head) * SLEN + s) * HD + d;
            *(uint2*)dst = make_uint2(pack_f16(rx, ry), pack_f16(rz, rw));
        } else {
            __half* dst = g_Kh + (((size_t)b * NKV + head) * SLEN + s) * HD + d;
            *(uint2*)dst = make_uint2(pack_f16(rx, ry), pack_f16(rz, rw));
        }
    } else if (n < HID + 1024) {         // V copy
        const int nn = n - HID - 512, head = nn >> 7, d = nn & 127;
        __half* dst = g_Vh + (((size_t)b * NKV + head) * SLEN + s) * HD + d;
        *(uint2*)dst = make_uint2(pack_f16(v.x, v.y), pack_f16(v.z, v.w));
    } else {                             // latent mid * gate -> Acth tail
        const float g = gate[0];
        __half* dst = g_Acth + (size_t)row * ACTN + HID + (n - HID - 1024);
        *(uint2*)dst = make_uint2(pack_f16(g * v.x, g * v.y),
                                  pack_f16(g * v.z, g * v.w));
    }
}

// ---------------------------------------------------------------------------
// Flash attention, fp16 mma + 3-stage cp.async K/V pipeline.
// CTA: 128 q-rows, 8 warps (m16 each), k-blocks of 64, causal skip.
// ---------------------------------------------------------------------------
#define LDT    136
#define QBYTES (128 * LDT * 2)            // 34816
#define KVT    (64 * LDT * 2)             // 17408 (one K or V tile)
#define ATTN_SMEM (QBYTES + 6 * KVT)      // 139264 B

__global__ __launch_bounds__(256, 1)
void attn_kernel()
{
    extern __shared__ __half smh[];
    const uint32_t smb = smem_u32(smh);
    __half* Qs = smh;                     // [128][LDT]
    const uint32_t kvb = smb + QBYTES;    // 3 stages of (K tile, V tile)

    const int qt  = (int)gridDim.x - 1 - (int)blockIdx.x;  // long blocks first
    const int bh  = blockIdx.y;
    const int b   = bh >> 4;
    const int h   = bh & 15;
    const int kvh = h >> 2;
    const int tid = threadIdx.x;
    const int wid = tid >> 5;
    const int lane = tid & 31;

    const __half* Qg = g_Qh + ((size_t)(b * NH + h) * SLEN + qt * 128) * HD;
    const __half* Kg = g_Kh + (size_t)(b * NKV + kvh) * SLEN * HD;
    const __half* Vg = g_Vh + (size_t)(b * NKV + kvh) * SLEN * HD;

    const int nblocks = 2 * qt + 2;

    // cp.async K/V stage loader: 64x128 each, 8 cp16 per thread
    const int crow = tid >> 2;
    const int ccolb = (tid & 3) * 32;
    auto cp_kv = [&](int kb) {
        if (kb < nblocks) {
            const uint32_t sb = kvb + (uint32_t)(kb % 3) * (2 * KVT);
            const __half* Kt = Kg + (size_t)kb * 64 * HD;
            const __half* Vt = Vg + (size_t)kb * 64 * HD;
#pragma unroll
            for (int t = 0; t < 4; t++) {
                const int col = ccolb + t * 8;
                const uint32_t so = (uint32_t)(crow * LDT + col) * 2;
                cp16(sb + so, Kt + crow * HD + col);
                cp16(sb + KVT + so, Vt + crow * HD + col);
            }
        }
        CP_COMMIT();
    };

    cp_kv(0);
    cp_kv(1);

    // stage Q tile (128x128 fp16) while K/V stream in
#pragma unroll
    for (int i = 0; i < 8; i++) {
        const int g = tid + i * 256;
        const int row = g >> 4, c8 = (g & 15) * 8;
        *(uint4*)(Qs + row * LDT + c8) = *(const uint4*)(Qg + row * HD + c8);
    }
    __syncthreads();

    // Q A-frags in registers (reused across all k-blocks)
    uint32_t qf[8][4];
    {
        const uint32_t qb = smb +
            (uint32_t)((wid * 16 + (lane & 15)) * LDT + ((lane >> 4) << 3)) * 2;
#pragma unroll
        for (int ks = 0; ks < 8; ks++)
            ldm_x4(qf[ks][0], qf[ks][1], qf[ks][2], qf[ks][3], qb + ks * 32);
    }

    float acc[16][4];
#pragma unroll
    for (int i = 0; i < 16; i++)
#pragma unroll
        for (int j = 0; j < 4; j++) acc[i][j] = 0.f;
    float rmax[2] = {-CUDART_INF_F, -CUDART_INF_F};
    float rsum[2] = {0.f, 0.f};

    const uint32_t koff =
        (uint32_t)(((lane & 7) + ((lane >> 4) << 3)) * LDT + (((lane >> 3) & 1) << 3)) * 2;
    const uint32_t voff =
        (uint32_t)((lane & 15) * LDT + ((lane >> 4) << 3)) * 2;

    for (int kb = 0; kb < nblocks; kb++) {
        CP_WAIT(1);                 // stage kb resident
        __syncthreads();            // all warps done with stage (kb-1)%3 compute
        cp_kv(kb + 2);              // prefetch into stage (kb+2)%3 (free since kb-1 done)

        const uint32_t sb = kvb + (uint32_t)(kb % 3) * (2 * KVT);
        const uint32_t kbase = sb + koff;
        const uint32_t vbase = sb + KVT + voff;

        // ---- S = Q K^T ----
        float s[8][4];
#pragma unroll
        for (int i = 0; i < 8; i++)
#pragma unroll
            for (int j = 0; j < 4; j++) s[i][j] = 0.f;

#pragma unroll
        for (int ks = 0; ks < 8; ks++) {
#pragma unroll
            for (int np = 0; np < 4; np++) {
                uint32_t k0, k1, k2, k3;
                ldm_x4(k0, k1, k2, k3,
                       kbase + (uint32_t)(np * 16 * LDT + ks * 16) * 2);
                uint32_t bA[2] = {k0, k1}, bB[2] = {k2, k3};
                mma16816h(s[np * 2],     qf[ks], bA);
                mma16816h(s[np * 2 + 1], qf[ks], bB);
            }
        }

        // ---- causal mask on diagonal-region blocks ----
        if (kb >= 2 * qt) {
            const int kc = kb * 64 + (lane & 3) * 2;
            const int mr = qt * 128 + wid * 16 + (lane >> 2);
#pragma unroll
            for (int nt = 0; nt < 8; nt++) {
                const int c = kc + nt * 8;
                if (c > mr)         s[nt][0] = -CUDART_INF_F;
                if (c + 1 > mr)     s[nt][1] = -CUDART_INF_F;
                if (c > mr + 8)     s[nt][2] = -CUDART_INF_F;
                if (c + 1 > mr + 8) s[nt][3] = -CUDART_INF_F;
            }
        }

        // ---- online softmax (rows r and r+8; 4-lane groups share a row) ----
#pragma unroll
        for (int hf = 0; hf < 2; hf++) {
            float mx = -CUDART_INF_F;
#pragma unroll
            for (int nt = 0; nt < 8; nt++)
                mx = fmaxf(mx, fmaxf(s[nt][2 * hf], s[nt][2 * hf + 1]));
            mx = fmaxf(mx, __shfl_xor_sync(0xffffffffu, mx, 1));
            mx = fmaxf(mx, __shfl_xor_sync(0xffffffffu, mx, 2));
            const float mnew = fmaxf(rmax[hf], mx);
            const float corr = __expf(rmax[hf] - mnew);
            rmax[hf] = mnew;
            float ps = 0.f;
#pragma unroll
            for (int nt = 0; nt < 8; nt++) {
                const float p0 = __expf(s[nt][2 * hf] - mnew);
                const float p1 = __expf(s[nt][2 * hf + 1] - mnew);
                s[nt][2 * hf] = p0; s[nt][2 * hf + 1] = p1;
                ps += p0 + p1;
            }
            ps += __shfl_xor_sync(0xffffffffu, ps, 1);
            ps += __shfl_xor_sync(0xffffffffu, ps, 2);
            rsum[hf] = rsum[hf] * corr + ps;
#pragma unroll
            for (int nt = 0; nt < 16; nt++) {
                acc[nt][2 * hf]     *= corr;
                acc[nt][2 * hf + 1] *= corr;
            }
        }

        // ---- pack P into fp16 A-frags ----
        uint32_t pa[4][4];
#pragma unroll
        for (int kt = 0; kt < 4; kt++) {
            pa[kt][0] = pack_f16(s[2 * kt][0],     s[2 * kt][1]);
            pa[kt][1] = pack_f16(s[2 * kt][2],     s[2 * kt][3]);
            pa[kt][2] = pack_f16(s[2 * kt + 1][0], s[2 * kt + 1][1]);
            pa[kt][3] = pack_f16(s[2 * kt + 1][2], s[2 * kt + 1][3]);
        }

        // ---- ctx += P V  (V B-frags via ldmatrix.trans) ----
#pragma unroll
        for (int np = 0; np < 8; np++) {
#pragma unroll
            for (int kt = 0; kt < 4; kt++) {
                uint32_t v0, v1, v2, v3;
                ldm_x4t(v0, v1, v2, v3,
                        vbase + (uint32_t)(kt * 16 * LDT + np * 16) * 2);
                uint32_t bA[2] = {v0, v1}, bB[2] = {v2, v3};
                mma16816h(acc[np * 2],     pa[kt], bA);
                mma16816h(acc[np * 2 + 1], pa[kt], bB);
            }
        }
    }

    // ---- epilogue: fp16 ctx into g_Acth ----
    const float inv0 = 1.f / rsum[0];
    const float inv1 = 1.f / rsum[1];
    const int mr = qt * 128 + wid * 16 + (lane >> 2);
    __half* op = g_Acth + ((size_t)b * SLEN + mr) * ACTN + h * HD;
#pragma unroll
    for (int nt = 0; nt < 16; nt++) {
        const int c = nt * 8 + (lane & 3) * 2;
        *(uint32_t*)(op + c) = pack_f16(acc[nt][0] * inv0, acc[nt][1] * inv0);
        *(uint32_t*)(op + (size_t)8 * ACTN + c) =
            pack_f16(acc[nt][2] * inv1, acc[nt][3] * inv1);
    }
}

// ---------------------------------------------------------------------------
extern "C" void kernel_launch(void* const* d_in, const int* in_sizes, int n_in,
                              void* d_out, int out_size)
{
    const float* hs     = (const float*)d_in[0];
    const float* cosb   = (const float*)d_in[1];
    const float* sinb   = (const float*)d_in[2];
    // d_in[3] = attention_mask (pure causal; implemented directly)
    const float* Wq     = (const float*)d_in[4];
    const float* Wk     = (const float*)d_in[5];
    const float* Wv     = (const float*)d_in[6];
    const float* Wo     = (const float*)d_in[7];
    const float* Wl_in  = (const float*)d_in[8];
    const float* Wl_out = (const float*)d_in[9];
    const float* gate   = (const float*)d_in[10];
    float* out = (float*)d_out;

    cudaFuncSetAttribute(attn_kernel,
                         cudaFuncAttributeMaxDynamicSharedMemorySize, ATTN_SMEM);
    cudaFuncSetAttribute(tc_gemm<0>,
                         cudaFuncAttributeMaxDynamicSharedMemorySize, GEMM_SMEM);
    cudaFuncSetAttribute(tc_gemm<1>,
                         cudaFuncAttributeMaxDynamicSharedMemorySize, GEMM_SMEM);

    // 0) fp32 -> fp16 conversion of hs + packed weights
    convert_inputs<<<CONV_BLOCKS, 256>>>(hs, Wq, Wk, Wv, Wo, Wl_in, Wl_out);
    // 1) fused [Q|K|V|latent_mid] projection
    tc_gemm<0><<<dim3(QKVLN / 128, ROWS / 128), 128, GEMM_SMEM>>>(nullptr);
    // 2) RoPE + repack -> fp16 Q/K/V (+ gate*mid into Acth tail)
    repack_rope<<<(ROWS * QKVLN / 4) / 256, 256>>>(cosb, sinb, gate);
    // 3) flash attention -> Acth[:, 0:2048]
    attn_kernel<<<dim3(SLEN / 128, BATCH * NH), 256, ATTN_SMEM>>>();
    // 4) out = Acth @ [Wo | Wl_out]^T
    tc_gemm<1><<<dim3(HID / 128, ROWS / 128), 128, GEMM_SMEM>>>(out);
}